// round 15
// baseline (speedup 1.0000x reference)
#include <cuda_runtime.h>
#include <cuda_bf16.h>
#include <math.h>
#include <stdint.h>

// Problem constants
#define BATCH 4
#define SEQ   2048
#define DMODEL 1024
#define NHEAD 16
#define HDIM  64
#define DFF   4096
#define TOKENS (BATCH*SEQ)       // 8192
#define MODW  6144               // 6*D

// ---------------- scratch (device globals; no allocations allowed) ----------
__device__ float g_mod[BATCH * MODW];
__device__ __nv_bfloat16 g_xn_hi[(size_t)TOKENS * DMODEL];
__device__ __nv_bfloat16 g_xn_lo[(size_t)TOKENS * DMODEL];
__device__ __nv_bfloat16 g_attn_hi[(size_t)TOKENS * DMODEL];
__device__ __nv_bfloat16 g_attn_lo[(size_t)TOKENS * DMODEL];
__device__ __nv_bfloat16 g_h_hi[(size_t)TOKENS * DFF];
__device__ __nv_bfloat16 g_h_lo[(size_t)TOKENS * DFF];
__device__ __nv_bfloat16 g_wqkv_hi[(size_t)DMODEL * 3 * DMODEL];
__device__ __nv_bfloat16 g_wqkv_lo[(size_t)DMODEL * 3 * DMODEL];
__device__ __nv_bfloat16 g_wout_hi[(size_t)DMODEL * DMODEL];
__device__ __nv_bfloat16 g_wout_lo[(size_t)DMODEL * DMODEL];
__device__ __nv_bfloat16 g_w1_hi[(size_t)DMODEL * DFF];
__device__ __nv_bfloat16 g_w1_lo[(size_t)DMODEL * DFF];
__device__ __nv_bfloat16 g_w2_hi[(size_t)DFF * DMODEL];
__device__ __nv_bfloat16 g_w2_lo[(size_t)DFF * DMODEL];
// attention operand planes, layout [B][H][S][HD]
__device__ __nv_bfloat16 g_q_hi[(size_t)TOKENS * DMODEL];
__device__ __nv_bfloat16 g_q_lo[(size_t)TOKENS * DMODEL];
__device__ __nv_bfloat16 g_k_hi[(size_t)TOKENS * DMODEL];
__device__ __nv_bfloat16 g_k_lo[(size_t)TOKENS * DMODEL];
__device__ __nv_bfloat16 g_v_hi[(size_t)TOKENS * DMODEL];
__device__ __nv_bfloat16 g_v_lo[(size_t)TOKENS * DMODEL];

// ---------------- generic helpers -------------------------------------------
__device__ __forceinline__ float warpSum(float v) {
    v += __shfl_xor_sync(0xffffffffu, v, 16);
    v += __shfl_xor_sync(0xffffffffu, v, 8);
    v += __shfl_xor_sync(0xffffffffu, v, 4);
    v += __shfl_xor_sync(0xffffffffu, v, 2);
    v += __shfl_xor_sync(0xffffffffu, v, 1);
    return v;
}

__device__ __forceinline__ float gelu_tanh(float x) {
    float x3 = x * x * x;
    return 0.5f * x * (1.0f + tanhf(0.7978845608028654f * (x + 0.044715f * x3)));
}

__device__ __forceinline__ uint32_t smem_u32(const void* p) {
    uint32_t a;
    asm("{ .reg .u64 t; cvta.to.shared.u64 t, %1; cvt.u32.u64 %0, t; }" : "=r"(a) : "l"(p));
    return a;
}

// fp32 -> (hi, lo) bf16 pair, packed two-at-a-time into b32 (a in low half)
__device__ __forceinline__ uint32_t split_pack(float a, float b, uint32_t& lo) {
    __nv_bfloat16 ha = __float2bfloat16(a), hb = __float2bfloat16(b);
    float ra = a - __bfloat162float(ha);
    float rb = b - __bfloat162float(hb);
    __nv_bfloat16 la = __float2bfloat16(ra), lb = __float2bfloat16(rb);
    lo = (uint32_t)__bfloat16_as_ushort(la) | ((uint32_t)__bfloat16_as_ushort(lb) << 16);
    return (uint32_t)__bfloat16_as_ushort(ha) | ((uint32_t)__bfloat16_as_ushort(hb) << 16);
}

__device__ __forceinline__ void split_store1(__nv_bfloat16* hi, __nv_bfloat16* lo,
                                             size_t idx, float v) {
    __nv_bfloat16 h = __float2bfloat16(v);
    hi[idx] = h;
    lo[idx] = __float2bfloat16(v - __bfloat162float(h));
}

__device__ __forceinline__ void split_store2(__nv_bfloat16* hi, __nv_bfloat16* lo,
                                             size_t idx, float a, float b) {
    __nv_bfloat16 ha = __float2bfloat16(a), hb = __float2bfloat16(b);
    __nv_bfloat162 hv; hv.x = ha; hv.y = hb;
    *(__nv_bfloat162*)&hi[idx] = hv;
    __nv_bfloat162 lv;
    lv.x = __float2bfloat16(a - __bfloat162float(ha));
    lv.y = __float2bfloat16(b - __bfloat162float(hb));
    *(__nv_bfloat162*)&lo[idx] = lv;
}

// ---------------- warp-level MMA primitives (sm_80+, no 'a' features) --------
__device__ __forceinline__ void ldsm4(uint32_t* r, uint32_t a) {
    asm volatile("ldmatrix.sync.aligned.m8n8.x4.shared.b16 {%0,%1,%2,%3}, [%4];"
        : "=r"(r[0]), "=r"(r[1]), "=r"(r[2]), "=r"(r[3]) : "r"(a));
}
__device__ __forceinline__ void ldsm4t(uint32_t* r, uint32_t a) {
    asm volatile("ldmatrix.sync.aligned.m8n8.x4.trans.shared.b16 {%0,%1,%2,%3}, [%4];"
        : "=r"(r[0]), "=r"(r[1]), "=r"(r[2]), "=r"(r[3]) : "r"(a));
}
__device__ __forceinline__ void mma16816(float* c, const uint32_t* a, const uint32_t* b) {
    asm volatile(
        "mma.sync.aligned.m16n8k16.row.col.f32.bf16.bf16.f32 "
        "{%0,%1,%2,%3}, {%4,%5,%6,%7}, {%8,%9}, {%0,%1,%2,%3};"
        : "+f"(c[0]), "+f"(c[1]), "+f"(c[2]), "+f"(c[3])
        : "r"(a[0]), "r"(a[1]), "r"(a[2]), "r"(a[3]), "r"(b[0]), "r"(b[1]));
}

__device__ __forceinline__ void cpa16(uint32_t s, const void* g) {
    asm volatile("cp.async.cg.shared.global [%0], [%1], 16;" :: "r"(s), "l"(g));
}
#define CP_COMMIT() asm volatile("cp.async.commit_group;" ::: "memory")
#define CP_WAIT1()  asm volatile("cp.async.wait_group 1;" ::: "memory")
#define CP_WAIT0()  asm volatile("cp.async.wait_group 0;" ::: "memory")

// ---------------- K-1: weight pre-split (fp32 -> bf16 hi/lo planes) ----------
__global__ void split_w(const float* __restrict__ W,
                        __nv_bfloat16* __restrict__ hi,
                        __nv_bfloat16* __restrict__ lo, int n4) {
    int i = blockIdx.x * 256 + threadIdx.x;
    if (i >= n4) return;
    float4 v = ((const float4*)W)[i];
    uint32_t l0, l1;
    uint32_t h0 = split_pack(v.x, v.y, l0);
    uint32_t h1 = split_pack(v.z, v.w, l1);
    ((uint2*)hi)[i] = make_uint2(h0, h1);
    ((uint2*)lo)[i] = make_uint2(l0, l1);
}

// ---------------- K0: adaLN modulation ---------------------------------------
__global__ void ada_kernel(const float* __restrict__ c,
                           const float* __restrict__ W,
                           const float* __restrict__ bias,
                           float* __restrict__ mod) {
    __shared__ float cs[BATCH * 1024];
    int tid = threadIdx.x;
    for (int i = tid; i < BATCH * 1024; i += 256) cs[i] = c[i];
    __syncthreads();
    int n = blockIdx.x * 256 + tid;
    float a0 = 0.f, a1 = 0.f, a2 = 0.f, a3 = 0.f;
    #pragma unroll 4
    for (int k = 0; k < 1024; k++) {
        float w = W[(size_t)k * MODW + n];
        a0 += cs[k] * w;
        a1 += cs[1024 + k] * w;
        a2 += cs[2048 + k] * w;
        a3 += cs[3072 + k] * w;
    }
    float bb = bias[n];
    mod[n] = a0 + bb;
    mod[MODW + n] = a1 + bb;
    mod[2 * MODW + n] = a2 + bb;
    mod[3 * MODW + n] = a3 + bb;
}

// ---------------- K1: LayerNorm + modulate -> split bf16 planes --------------
__global__ void ln_mod_kernel(const float* __restrict__ x,
                              const float* __restrict__ w,
                              const float* __restrict__ mod,
                              int shOff, int scOff,
                              __nv_bfloat16* __restrict__ ohi,
                              __nv_bfloat16* __restrict__ olo) {
    int token = blockIdx.x;
    int b = token >> 11;
    int tid = threadIdx.x;
    const float* xr = x + (size_t)token * DMODEL;
    float4 v = ((const float4*)xr)[tid];
    float lsum = v.x + v.y + v.z + v.w;
    float lsq = v.x * v.x + v.y * v.y + v.z * v.z + v.w * v.w;
    __shared__ float s1[8], s2[8];
    float ws = warpSum(lsum), wq = warpSum(lsq);
    int warp = tid >> 5, lane = tid & 31;
    if (lane == 0) { s1[warp] = ws; s2[warp] = wq; }
    __syncthreads();
    __shared__ float s_mu, s_rstd;
    if (tid == 0) {
        float ts = 0.f, tq = 0.f;
        #pragma unroll
        for (int i = 0; i < 8; i++) { ts += s1[i]; tq += s2[i]; }
        float mu = ts * (1.0f / DMODEL);
        float var = tq * (1.0f / DMODEL) - mu * mu;
        s_mu = mu;
        s_rstd = rsqrtf(var + 1e-5f);
    }
    __syncthreads();
    float mu = s_mu, rstd = s_rstd;
    const float* mrow = mod + (size_t)b * MODW;
    size_t rowoff = (size_t)token * DMODEL;
    int d = tid * 4;
    float4 wv = *(const float4*)&w[d];
    float4 sc = *(const float4*)&mrow[scOff + d];
    float4 sh = *(const float4*)&mrow[shOff + d];
    float o0 = (v.x - mu) * rstd * wv.x * (1.f + sc.x) + sh.x;
    float o1 = (v.y - mu) * rstd * wv.y * (1.f + sc.y) + sh.y;
    float o2 = (v.z - mu) * rstd * wv.z * (1.f + sc.z) + sh.z;
    float o3 = (v.w - mu) * rstd * wv.w * (1.f + sc.w) + sh.w;
    split_store2(ohi, olo, rowoff + d, o0, o1);
    split_store2(ohi, olo, rowoff + d + 2, o2, o3);
}

// ---------------- split-bf16 HMMA GEMM common pieces -------------------------
#define AST    80
#define BSTB   272
#define A_LO_OFF 10240
#define B_HI_OFF 20480
#define STAGE  37888
#define GEMM_SMEM (3 * STAGE)   // 113664, 3-stage

// mainloop macro: leaves result in acc[2][8][4]; K/N compile-time-ish ints
#define GEMM_MAINLOOP(Ahg, Alg, Bhg, Blg, K, N)                                   \
    float acc[2][8][4];                                                            \
    _Pragma("unroll")                                                              \
    for (int i = 0; i < 2; i++)                                                    \
        _Pragma("unroll")                                                          \
        for (int j = 0; j < 8; j++)                                                \
            _Pragma("unroll")                                                      \
            for (int k = 0; k < 4; k++) acc[i][j][k] = 0.f;                        \
    int s0i = tid * 2;                                                             \
    int arow0 = s0i >> 2,  aoff0 = s0i & 3;                                        \
    int arow1 = (s0i+1) >> 2, aoff1 = (s0i+1) & 3;                                 \
    int brow0 = s0i >> 4,  boff0 = s0i & 15;                                       \
    int brow1 = (s0i+1) >> 4, boff1 = (s0i+1) & 15;                                \
    uint32_t aBase = sb + (uint32_t)(wm * 32 + (lane & 15)) * AST                  \
                   + (uint32_t)((lane >> 4) * 8) * 2;                              \
    int bg = lane >> 3;                                                            \
    uint32_t bBase = sb + B_HI_OFF + (uint32_t)((bg & 1) * 8 + (lane & 7)) * BSTB  \
                   + (uint32_t)(wn * 64 + ((bg >> 1) & 1) * 8) * 2;                \
    const int nc = (K) >> 5;                                                       \
    auto load_stage = [&](int c, int st) {                                         \
        int k0 = c << 5;                                                           \
        uint32_t sA = sb + st * STAGE;                                             \
        uint32_t sB = sA + B_HI_OFF;                                               \
        cpa16(sA + arow0 * AST + aoff0 * 16,                                       \
              Ahg + (size_t)(m0 + arow0) * (K) + k0 + aoff0 * 8);                  \
        cpa16(sA + arow0 * AST + aoff0 * 16 + A_LO_OFF,                            \
              Alg + (size_t)(m0 + arow0) * (K) + k0 + aoff0 * 8);                  \
        cpa16(sA + arow1 * AST + aoff1 * 16,                                       \
              Ahg + (size_t)(m0 + arow1) * (K) + k0 + aoff1 * 8);                  \
        cpa16(sA + arow1 * AST + aoff1 * 16 + A_LO_OFF,                            \
              Alg + (size_t)(m0 + arow1) * (K) + k0 + aoff1 * 8);                  \
        cpa16(sB + brow0 * BSTB + boff0 * 16,                                      \
              Bhg + (size_t)(k0 + brow0) * (N) + n0 + boff0 * 8);                  \
        cpa16(sB + brow0 * BSTB + boff0 * 16 + 8704,                               \
              Blg + (size_t)(k0 + brow0) * (N) + n0 + boff0 * 8);                  \
        cpa16(sB + brow1 * BSTB + boff1 * 16,                                      \
              Bhg + (size_t)(k0 + brow1) * (N) + n0 + boff1 * 8);                  \
        cpa16(sB + brow1 * BSTB + boff1 * 16 + 8704,                               \
              Blg + (size_t)(k0 + brow1) * (N) + n0 + boff1 * 8);                  \
    };                                                                             \
    load_stage(0, 0); CP_COMMIT();                                                 \
    load_stage(1, 1); CP_COMMIT();                                                 \
    for (int c = 0; c < nc; c++) {                                                 \
        if (c + 1 < nc) { CP_WAIT1(); } else { CP_WAIT0(); }                       \
        __syncthreads();                                                           \
        if (c + 2 < nc) { load_stage(c + 2, (c + 2) % 3); CP_COMMIT(); }           \
        uint32_t stOff = (uint32_t)(c % 3) * STAGE;                                \
        _Pragma("unroll")                                                          \
        for (int ks = 0; ks < 2; ks++) {                                           \
            uint32_t ah[2][4], al[2][4];                                           \
            _Pragma("unroll")                                                      \
            for (int mt = 0; mt < 2; mt++) {                                       \
                ldsm4(ah[mt], aBase + stOff + mt * 16 * AST + ks * 32);            \
                ldsm4(al[mt], aBase + stOff + A_LO_OFF + mt * 16 * AST + ks * 32); \
            }                                                                      \
            _Pragma("unroll")                                                      \
            for (int q = 0; q < 4; q++) {                                          \
                uint32_t bh[4], bl[4];                                             \
                ldsm4t(bh, bBase + stOff + q * 32 + ks * 16 * BSTB);               \
                ldsm4t(bl, bBase + stOff + 8704 + q * 32 + ks * 16 * BSTB);        \
                _Pragma("unroll")                                                  \
                for (int mt = 0; mt < 2; mt++) {                                   \
                    mma16816(acc[mt][2 * q],     ah[mt], bh);                      \
                    mma16816(acc[mt][2 * q],     ah[mt], bl);                      \
                    mma16816(acc[mt][2 * q],     al[mt], bh);                      \
                    mma16816(acc[mt][2 * q + 1], ah[mt], bh + 2);                  \
                    mma16816(acc[mt][2 * q + 1], ah[mt], bl + 2);                  \
                    mma16816(acc[mt][2 * q + 1], al[mt], bh + 2);                  \
                }                                                                  \
            }                                                                      \
        }                                                                          \
    }

template <int EPI>
__device__ __forceinline__ float epi_apply(float v, int m, int n, int N,
        const float* __restrict__ bias, const float* __restrict__ resid,
        const float* __restrict__ mod, int modOff) {
    if (EPI == 2) v = resid[(size_t)m * N + n]
                    + mod[(size_t)(m >> 11) * MODW + modOff + n] * v;
    if (EPI == 3) v = resid[(size_t)m * N + n]
                    + mod[(size_t)(m >> 11) * MODW + modOff + n] * (v + bias[n]);
    return v;
}

// EPI 1: Chi/Clo(bf16 split) = gelu(A@B + bias)
// EPI 2: C = resid + mod[b, modOff+n] * (A@B)              (N == 1024)
// EPI 3: C = resid + mod[b, modOff+n] * (A@B + bias)       (N == 1024)
template <int EPI>
__global__ void __launch_bounds__(256, 2)
mma_gemm(const __nv_bfloat16* __restrict__ Ahg, const __nv_bfloat16* __restrict__ Alg,
         const __nv_bfloat16* __restrict__ Bhg, const __nv_bfloat16* __restrict__ Blg,
         float* __restrict__ C,
         __nv_bfloat16* __restrict__ Chi, __nv_bfloat16* __restrict__ Clo,
         int M, int N, int K,
         const float* __restrict__ bias,
         const float* __restrict__ resid,
         const float* __restrict__ mod, int modOff) {
    extern __shared__ char smem[];
    uint32_t sb = smem_u32(smem);
    int tid = threadIdx.x, lane = tid & 31, wid = tid >> 5;
    int wm = wid >> 1, wn = wid & 1;
    int m0 = blockIdx.y * 128, n0 = blockIdx.x * 128;

    GEMM_MAINLOOP(Ahg, Alg, Bhg, Blg, K, N)

    int r0 = lane >> 2, cp2 = (lane & 3) * 2;
    #pragma unroll
    for (int mt = 0; mt < 2; mt++) {
        #pragma unroll
        for (int nt = 0; nt < 8; nt++) {
            int m = m0 + wm * 32 + mt * 16 + r0;
            int n = n0 + wn * 64 + nt * 8 + cp2;
            float* cacc = acc[mt][nt];
            if (EPI == 1) {
                float v00 = gelu_tanh(cacc[0] + bias[n]);
                float v01 = gelu_tanh(cacc[1] + bias[n + 1]);
                float v10 = gelu_tanh(cacc[2] + bias[n]);
                float v11 = gelu_tanh(cacc[3] + bias[n + 1]);
                split_store2(Chi, Clo, (size_t)m * N + n, v00, v01);
                split_store2(Chi, Clo, (size_t)(m + 8) * N + n, v10, v11);
            } else {
                float2 o0, o1;
                o0.x = epi_apply<EPI>(cacc[0], m, n,     N, bias, resid, mod, modOff);
                o0.y = epi_apply<EPI>(cacc[1], m, n + 1, N, bias, resid, mod, modOff);
                o1.x = epi_apply<EPI>(cacc[2], m + 8, n,     N, bias, resid, mod, modOff);
                o1.y = epi_apply<EPI>(cacc[3], m + 8, n + 1, N, bias, resid, mod, modOff);
                *(float2*)&C[(size_t)m * N + n] = o0;
                *(float2*)&C[(size_t)(m + 8) * N + n] = o1;
            }
        }
    }
}

// ---------------- K2: QKV GEMM with fused RMSNorm + RoPE + split epilogue ----
// Each warp's 64 cols = exactly one (t, head): t = q/k/v. Outputs planes
// [B][H][S][HD]; q pre-scaled by 0.125*log2(e).
__global__ void __launch_bounds__(256, 2)
mma_gemm_qkv(const __nv_bfloat16* __restrict__ Ahg, const __nv_bfloat16* __restrict__ Alg,
             const __nv_bfloat16* __restrict__ Bhg, const __nv_bfloat16* __restrict__ Blg,
             const float* __restrict__ cosb, const float* __restrict__ sinb,
             const float* __restrict__ qw, const float* __restrict__ kw,
             __nv_bfloat16* __restrict__ qh, __nv_bfloat16* __restrict__ ql,
             __nv_bfloat16* __restrict__ kh, __nv_bfloat16* __restrict__ kl,
             __nv_bfloat16* __restrict__ vh, __nv_bfloat16* __restrict__ vl) {
    extern __shared__ char smem[];
    uint32_t sb = smem_u32(smem);
    int tid = threadIdx.x, lane = tid & 31, wid = tid >> 5;
    int wm = wid >> 1, wn = wid & 1;
    int m0 = blockIdx.y * 128, n0 = blockIdx.x * 128;
    const int K = DMODEL, N = 3 * DMODEL;

    GEMM_MAINLOOP(Ahg, Alg, Bhg, Blg, K, N)

    int r0 = lane >> 2, cp2 = (lane & 3) * 2;
    int nw = n0 + wn * 64;
    int t = nw >> 10;                 // 0=q 1=k 2=v
    int hh = (nw >> 6) & 15;          // head
    #pragma unroll
    for (int mt = 0; mt < 2; mt++) {
        int mA = m0 + wm * 32 + mt * 16 + r0;
        int mB = mA + 8;
        int sA = mA & (SEQ - 1), sB2 = mB & (SEQ - 1);
        size_t baseA = (((size_t)((mA >> 11) * NHEAD + hh)) * SEQ + sA) * HDIM;
        size_t baseB = (((size_t)((mB >> 11) * NHEAD + hh)) * SEQ + sB2) * HDIM;
        if (t == 2) {
            #pragma unroll
            for (int nt = 0; nt < 8; nt++) {
                int d = nt * 8 + cp2;
                split_store2(vh, vl, baseA + d, acc[mt][nt][0], acc[mt][nt][1]);
                split_store2(vh, vl, baseB + d, acc[mt][nt][2], acc[mt][nt][3]);
            }
        } else {
            const float* w = (t == 0) ? qw : kw;
            float ss0 = 0.f, ss1 = 0.f;
            #pragma unroll
            for (int nt = 0; nt < 8; nt++) {
                ss0 += acc[mt][nt][0] * acc[mt][nt][0] + acc[mt][nt][1] * acc[mt][nt][1];
                ss1 += acc[mt][nt][2] * acc[mt][nt][2] + acc[mt][nt][3] * acc[mt][nt][3];
            }
            ss0 += __shfl_xor_sync(0xffffffffu, ss0, 1);
            ss0 += __shfl_xor_sync(0xffffffffu, ss0, 2);
            ss1 += __shfl_xor_sync(0xffffffffu, ss1, 1);
            ss1 += __shfl_xor_sync(0xffffffffu, ss1, 2);
            float ri0 = rsqrtf(ss0 * (1.0f / HDIM) + 1e-6f);
            float ri1 = rsqrtf(ss1 * (1.0f / HDIM) + 1e-6f);
            float xa[16], xb[16];
            #pragma unroll
            for (int nt = 0; nt < 8; nt++) {
                int d = nt * 8 + cp2;
                float w0 = w[d], w1 = w[d + 1];
                xa[2 * nt]     = acc[mt][nt][0] * ri0 * w0;
                xa[2 * nt + 1] = acc[mt][nt][1] * ri0 * w1;
                xb[2 * nt]     = acc[mt][nt][2] * ri1 * w0;
                xb[2 * nt + 1] = acc[mt][nt][3] * ri1 * w1;
            }
            const float SC = (t == 0) ? 0.125f * 1.4426950408889634f : 1.0f;
            __nv_bfloat16* oh = (t == 0) ? qh : kh;
            __nv_bfloat16* ol = (t == 0) ? ql : kl;
            #pragma unroll
            for (int nt = 0; nt < 8; nt++) {
                int d = nt * 8 + cp2;
                int p = nt ^ 4;
                float sg = (nt < 4) ? -1.f : 1.f;
                float2 cA = *(const float2*)&cosb[sA * HDIM + d];
                float2 sAv = *(const float2*)&sinb[sA * HDIM + d];
                float2 cB = *(const float2*)&cosb[sB2 * HDIM + d];
                float2 sBv = *(const float2*)&sinb[sB2 * HDIM + d];
                float oA0 = (xa[2 * nt] * cA.x + sg * xa[2 * p] * sAv.x) * SC;
                float oA1 = (xa[2 * nt + 1] * cA.y + sg * xa[2 * p + 1] * sAv.y) * SC;
                float oB0 = (xb[2 * nt] * cB.x + sg * xb[2 * p] * sBv.x) * SC;
                float oB1 = (xb[2 * nt + 1] * cB.y + sg * xb[2 * p + 1] * sBv.y) * SC;
                split_store2(oh, ol, baseA + d, oA0, oA1);
                split_store2(oh, ol, baseB + d, oB0, oB1);
            }
        }
    }
}

// ---------------- K4: HMMA flash attention (3-stage KV pipeline) -------------
#define FST   144
#define FSTAGE 36864
#define FLASH_SMEM (3 * FSTAGE)   // 110592

__global__ void __launch_bounds__(256, 2)
flash_mma(const __nv_bfloat16* __restrict__ qh, const __nv_bfloat16* __restrict__ ql,
          const __nv_bfloat16* __restrict__ kh, const __nv_bfloat16* __restrict__ kl,
          const __nv_bfloat16* __restrict__ vh, const __nv_bfloat16* __restrict__ vl,
          __nv_bfloat16* __restrict__ ohi, __nv_bfloat16* __restrict__ olo) {
    extern __shared__ char smem[];
    uint32_t sb = smem_u32(smem);
    int tid = threadIdx.x, lane = tid & 31, wid = tid >> 5;
    int bhid = blockIdx.x;               // b*16 + h
    int h = bhid & 15, b = bhid >> 4;
    int q0 = blockIdx.y * 128;
    size_t hoff = (size_t)bhid * SEQ * HDIM;

    // ---- Q -> smem (stage0/1 region) -> registers ----
    #pragma unroll
    for (int i = 0; i < 4; i++) {
        int c = tid + i * 256;
        int row = c >> 3, col = c & 7;
        cpa16(sb + row * FST + col * 16, qh + hoff + (size_t)(q0 + row) * HDIM + col * 8);
        cpa16(sb + 18432 + row * FST + col * 16, ql + hoff + (size_t)(q0 + row) * HDIM + col * 8);
    }
    CP_COMMIT(); CP_WAIT0();
    __syncthreads();
    uint32_t qfh[4][4], qfl[4][4];
    {
        uint32_t aB = sb + (uint32_t)(wid * 16 + (lane & 15)) * FST + (uint32_t)((lane >> 4) * 16);
        #pragma unroll
        for (int kt = 0; kt < 4; kt++) {
            ldsm4(qfh[kt], aB + kt * 32);
            ldsm4(qfl[kt], aB + 18432 + kt * 32);
        }
    }
    __syncthreads();

    float o[8][4];
    #pragma unroll
    for (int i = 0; i < 8; i++)
        #pragma unroll
        for (int j = 0; j < 4; j++) o[i][j] = 0.f;
    float m0 = -1e30f, m1 = -1e30f, l0 = 0.f, l1 = 0.f;

    uint32_t kB = (uint32_t)((lane & 7) + ((lane >> 4) << 3)) * FST + (uint32_t)(((lane >> 3) & 1) << 4);
    int bg = lane >> 3;
    uint32_t vB = (uint32_t)((bg & 1) * 8 + (lane & 7)) * FST + (uint32_t)(((bg >> 1)) << 4);

    auto load_kv = [&](int t, int st) {
        int k0 = t * 64;
        uint32_t sbase = sb + st * FSTAGE;
        #pragma unroll
        for (int i = 0; i < 2; i++) {
            int c = tid + i * 256;
            int row = c >> 3, col = c & 7;
            size_t goff = hoff + (size_t)(k0 + row) * HDIM + col * 8;
            uint32_t d = sbase + row * FST + col * 16;
            cpa16(d, kh + goff);
            cpa16(d + 9216, kl + goff);
            cpa16(d + 18432, vh + goff);
            cpa16(d + 27648, vl + goff);
        }
    };

    load_kv(0, 0); CP_COMMIT();
    load_kv(1, 1); CP_COMMIT();

    const int NT = SEQ / 64;
    for (int t = 0; t < NT; t++) {
        if (t + 1 < NT) { CP_WAIT1(); } else { CP_WAIT0(); }
        __syncthreads();
        if (t + 2 < NT) { load_kv(t + 2, (t + 2) % 3); CP_COMMIT(); }
        uint32_t stB = sb + (uint32_t)(t % 3) * FSTAGE;

        // ---- S = Q K^T (split, 3 passes) ----
        float s[8][4];
        #pragma unroll
        for (int i = 0; i < 8; i++)
            #pragma unroll
            for (int j = 0; j < 4; j++) s[i][j] = 0.f;
        #pragma unroll
        for (int kt = 0; kt < 4; kt++) {
            #pragma unroll
            for (int kg = 0; kg < 4; kg++) {
                uint32_t fh[4], fl[4];
                uint32_t addr = stB + kB + kg * (16 * FST) + kt * 32;
                ldsm4(fh, addr);
                ldsm4(fl, addr + 9216);
                mma16816(s[kg * 2],     qfh[kt], fh);
                mma16816(s[kg * 2],     qfh[kt], fl);
                mma16816(s[kg * 2],     qfl[kt], fh);
                mma16816(s[kg * 2 + 1], qfh[kt], fh + 2);
                mma16816(s[kg * 2 + 1], qfh[kt], fl + 2);
                mma16816(s[kg * 2 + 1], qfl[kt], fh + 2);
            }
        }

        // ---- online softmax (base-2; scale folded into Q) ----
        float tm0 = -1e30f, tm1 = -1e30f;
        #pragma unroll
        for (int i = 0; i < 8; i++) {
            tm0 = fmaxf(tm0, fmaxf(s[i][0], s[i][1]));
            tm1 = fmaxf(tm1, fmaxf(s[i][2], s[i][3]));
        }
        tm0 = fmaxf(tm0, __shfl_xor_sync(0xffffffffu, tm0, 1));
        tm0 = fmaxf(tm0, __shfl_xor_sync(0xffffffffu, tm0, 2));
        tm1 = fmaxf(tm1, __shfl_xor_sync(0xffffffffu, tm1, 1));
        tm1 = fmaxf(tm1, __shfl_xor_sync(0xffffffffu, tm1, 2));
        float mn0 = fmaxf(m0, tm0), mn1 = fmaxf(m1, tm1);
        float al0 = exp2f(m0 - mn0), al1 = exp2f(m1 - mn1);
        float ts0 = 0.f, ts1 = 0.f;
        #pragma unroll
        for (int i = 0; i < 8; i++) {
            s[i][0] = exp2f(s[i][0] - mn0);
            s[i][1] = exp2f(s[i][1] - mn0);
            s[i][2] = exp2f(s[i][2] - mn1);
            s[i][3] = exp2f(s[i][3] - mn1);
            ts0 += s[i][0] + s[i][1];
            ts1 += s[i][2] + s[i][3];
        }
        ts0 += __shfl_xor_sync(0xffffffffu, ts0, 1);
        ts0 += __shfl_xor_sync(0xffffffffu, ts0, 2);
        ts1 += __shfl_xor_sync(0xffffffffu, ts1, 1);
        ts1 += __shfl_xor_sync(0xffffffffu, ts1, 2);
        l0 = l0 * al0 + ts0;
        l1 = l1 * al1 + ts1;
        m0 = mn0; m1 = mn1;
        #pragma unroll
        for (int i = 0; i < 8; i++) {
            o[i][0] *= al0; o[i][1] *= al0;
            o[i][2] *= al1; o[i][3] *= al1;
        }

        // ---- O += P V (split P in-register, split V, 3 passes) ----
        #pragma unroll
        for (int kt2 = 0; kt2 < 4; kt2++) {
            uint32_t ph[4], pl[4];
            ph[0] = split_pack(s[kt2 * 2][0],     s[kt2 * 2][1],     pl[0]);
            ph[1] = split_pack(s[kt2 * 2][2],     s[kt2 * 2][3],     pl[1]);
            ph[2] = split_pack(s[kt2 * 2 + 1][0], s[kt2 * 2 + 1][1], pl[2]);
            ph[3] = split_pack(s[kt2 * 2 + 1][2], s[kt2 * 2 + 1][3], pl[3]);
            #pragma unroll
            for (int nq = 0; nq < 4; nq++) {
                uint32_t wh[4], wl[4];
                uint32_t addr = stB + 18432 + vB + kt2 * (16 * FST) + nq * 32;
                ldsm4t(wh, addr);
                ldsm4t(wl, addr + 9216);
                mma16816(o[nq * 2],     ph, wh);
                mma16816(o[nq * 2],     pl, wh);
                mma16816(o[nq * 2],     ph, wl);
                mma16816(o[nq * 2 + 1], ph, wh + 2);
                mma16816(o[nq * 2 + 1], pl, wh + 2);
                mma16816(o[nq * 2 + 1], ph, wl + 2);
            }
        }
    }

    // ---- normalize + split store to attn planes [token][D] ----
    float inv0 = 1.f / l0, inv1 = 1.f / l1;
    int r0 = lane >> 2, cp2 = (lane & 3) * 2;
    int row0 = q0 + wid * 16 + r0;
    size_t t0 = (size_t)(b * SEQ + row0) * DMODEL + h * HDIM;
    size_t t1 = t0 + 8 * DMODEL;
    #pragma unroll
    for (int nt = 0; nt < 8; nt++) {
        split_store2(ohi, olo, t0 + nt * 8 + cp2, o[nt][0] * inv0, o[nt][1] * inv0);
        split_store2(ohi, olo, t1 + nt * 8 + cp2, o[nt][2] * inv1, o[nt][3] * inv1);
    }
}

// ---------------- launcher ---------------------------------------------------
extern "C" void kernel_launch(void* const* d_in, const int* in_sizes, int n_in,
                              void* d_out, int out_size) {
    const float* x       = (const float*)d_in[0];
    const float* cosb    = (const float*)d_in[1];
    const float* sinb    = (const float*)d_in[2];
    const float* c       = (const float*)d_in[3];
    const float* norm1_w = (const float*)d_in[4];
    const float* Wqkv    = (const float*)d_in[5];
    const float* Wout    = (const float*)d_in[6];
    const float* q_norm_w= (const float*)d_in[7];
    const float* k_norm_w= (const float*)d_in[8];
    const float* norm2_w = (const float*)d_in[9];
    const float* W1      = (const float*)d_in[10];
    const float* b1      = (const float*)d_in[11];
    const float* W2      = (const float*)d_in[12];
    const float* b2      = (const float*)d_in[13];
    const float* ada_W   = (const float*)d_in[14];
    const float* ada_b   = (const float*)d_in[15];
    float* out = (float*)d_out;

    float *mod_p;
    __nv_bfloat16 *xnh, *xnl, *ath, *atl, *hh, *hl;
    __nv_bfloat16 *wqh, *wql, *woh, *wol, *w1h, *w1l, *w2h, *w2l;
    __nv_bfloat16 *qph, *qpl, *kph, *kpl, *vph, *vpl;
    cudaGetSymbolAddress((void**)&mod_p, g_mod);
    cudaGetSymbolAddress((void**)&xnh, g_xn_hi);
    cudaGetSymbolAddress((void**)&xnl, g_xn_lo);
    cudaGetSymbolAddress((void**)&ath, g_attn_hi);
    cudaGetSymbolAddress((void**)&atl, g_attn_lo);
    cudaGetSymbolAddress((void**)&hh, g_h_hi);
    cudaGetSymbolAddress((void**)&hl, g_h_lo);
    cudaGetSymbolAddress((void**)&wqh, g_wqkv_hi);
    cudaGetSymbolAddress((void**)&wql, g_wqkv_lo);
    cudaGetSymbolAddress((void**)&woh, g_wout_hi);
    cudaGetSymbolAddress((void**)&wol, g_wout_lo);
    cudaGetSymbolAddress((void**)&w1h, g_w1_hi);
    cudaGetSymbolAddress((void**)&w1l, g_w1_lo);
    cudaGetSymbolAddress((void**)&w2h, g_w2_hi);
    cudaGetSymbolAddress((void**)&w2l, g_w2_lo);
    cudaGetSymbolAddress((void**)&qph, g_q_hi);
    cudaGetSymbolAddress((void**)&qpl, g_q_lo);
    cudaGetSymbolAddress((void**)&kph, g_k_hi);
    cudaGetSymbolAddress((void**)&kpl, g_k_lo);
    cudaGetSymbolAddress((void**)&vph, g_v_hi);
    cudaGetSymbolAddress((void**)&vpl, g_v_lo);

    cudaFuncSetAttribute(mma_gemm<1>, cudaFuncAttributeMaxDynamicSharedMemorySize, GEMM_SMEM);
    cudaFuncSetAttribute(mma_gemm<2>, cudaFuncAttributeMaxDynamicSharedMemorySize, GEMM_SMEM);
    cudaFuncSetAttribute(mma_gemm<3>, cudaFuncAttributeMaxDynamicSharedMemorySize, GEMM_SMEM);
    cudaFuncSetAttribute(mma_gemm_qkv, cudaFuncAttributeMaxDynamicSharedMemorySize, GEMM_SMEM);
    cudaFuncSetAttribute(flash_mma, cudaFuncAttributeMaxDynamicSharedMemorySize, FLASH_SMEM);

    // weight pre-split
    split_w<<<(DMODEL*3*DMODEL/4)/256, 256>>>(Wqkv, wqh, wql, DMODEL*3*DMODEL/4);
    split_w<<<(DMODEL*DMODEL/4)/256, 256>>>(Wout, woh, wol, DMODEL*DMODEL/4);
    split_w<<<(DMODEL*DFF/4)/256, 256>>>(W1, w1h, w1l, DMODEL*DFF/4);
    split_w<<<(DFF*DMODEL/4)/256, 256>>>(W2, w2h, w2l, DFF*DMODEL/4);

    // K0: modulation
    ada_kernel<<<MODW / 256, 256>>>(c, ada_W, ada_b, mod_p);

    // K1: LN1 + modulate -> xn split planes
    ln_mod_kernel<<<TOKENS, 256>>>(x, norm1_w, mod_p, 0, 1024, xnh, xnl);

    // K2: QKV GEMM + fused RMSNorm/RoPE/split -> q/k/v planes [B][H][S][HD]
    mma_gemm_qkv<<<dim3(3 * DMODEL / 128, TOKENS / 128), 256, GEMM_SMEM>>>(
        xnh, xnl, wqh, wql, cosb, sinb, q_norm_w, k_norm_w,
        qph, qpl, kph, kpl, vph, vpl);

    // K4: HMMA flash attention -> attn split planes
    flash_mma<<<dim3(BATCH * NHEAD, SEQ / 128), 256, FLASH_SMEM>>>(
        qph, qpl, kph, kpl, vph, vpl, ath, atl);

    // K5: Wout GEMM + gated residual (g_msa @2048) -> out fp32
    mma_gemm<2><<<dim3(DMODEL / 128, TOKENS / 128), 256, GEMM_SMEM>>>(
        ath, atl, woh, wol, out, nullptr, nullptr,
        TOKENS, DMODEL, DMODEL, nullptr, x, mod_p, 2048);

    // K6: LN2 + modulate -> xn split planes
    ln_mod_kernel<<<TOKENS, 256>>>(out, norm2_w, mod_p, 3072, 4096, xnh, xnl);

    // K7: MLP up GEMM + bias + gelu -> h split planes
    mma_gemm<1><<<dim3(DFF / 128, TOKENS / 128), 256, GEMM_SMEM>>>(
        xnh, xnl, w1h, w1l, nullptr, hh, hl,
        TOKENS, DFF, DMODEL, b1, nullptr, nullptr, 0);

    // K8: MLP down GEMM + bias + gated residual (g_mlp @5120), in-place on out
    mma_gemm<3><<<dim3(DMODEL / 128, TOKENS / 128), 256, GEMM_SMEM>>>(
        hh, hl, w2h, w2l, out, nullptr, nullptr,
        TOKENS, DMODEL, DFF, b2, out, mod_p, 5120);
}

// round 16
// speedup vs baseline: 1.5312x; 1.5312x over previous
#include <cuda_runtime.h>
#include <cuda_bf16.h>
#include <math.h>
#include <stdint.h>

// Problem constants
#define BATCH 4
#define SEQ   2048
#define DMODEL 1024
#define NHEAD 16
#define HDIM  64
#define DFF   4096
#define TOKENS (BATCH*SEQ)       // 8192
#define MODW  6144               // 6*D

// ---------------- scratch (device globals; no allocations allowed) ----------
__device__ float g_mod[BATCH * MODW];
__device__ __nv_bfloat16 g_xn_hi[(size_t)TOKENS * DMODEL];
__device__ __nv_bfloat16 g_xn_lo[(size_t)TOKENS * DMODEL];
__device__ __nv_bfloat16 g_attn_hi[(size_t)TOKENS * DMODEL];
__device__ __nv_bfloat16 g_attn_lo[(size_t)TOKENS * DMODEL];
__device__ __nv_bfloat16 g_h_hi[(size_t)TOKENS * DFF];
__device__ __nv_bfloat16 g_h_lo[(size_t)TOKENS * DFF];
__device__ __nv_bfloat16 g_wqkv_hi[(size_t)DMODEL * 3 * DMODEL];
__device__ __nv_bfloat16 g_wqkv_lo[(size_t)DMODEL * 3 * DMODEL];
__device__ __nv_bfloat16 g_wout_hi[(size_t)DMODEL * DMODEL];
__device__ __nv_bfloat16 g_wout_lo[(size_t)DMODEL * DMODEL];
__device__ __nv_bfloat16 g_w1_hi[(size_t)DMODEL * DFF];
__device__ __nv_bfloat16 g_w1_lo[(size_t)DMODEL * DFF];
__device__ __nv_bfloat16 g_w2_hi[(size_t)DFF * DMODEL];
__device__ __nv_bfloat16 g_w2_lo[(size_t)DFF * DMODEL];
// attention operand planes, layout [B][H][S][HD]
__device__ __nv_bfloat16 g_q_hi[(size_t)TOKENS * DMODEL];
__device__ __nv_bfloat16 g_q_lo[(size_t)TOKENS * DMODEL];
__device__ __nv_bfloat16 g_k_hi[(size_t)TOKENS * DMODEL];
__device__ __nv_bfloat16 g_k_lo[(size_t)TOKENS * DMODEL];
__device__ __nv_bfloat16 g_v_hi[(size_t)TOKENS * DMODEL];
__device__ __nv_bfloat16 g_v_lo[(size_t)TOKENS * DMODEL];

// ---------------- generic helpers -------------------------------------------
__device__ __forceinline__ float warpSum(float v) {
    v += __shfl_xor_sync(0xffffffffu, v, 16);
    v += __shfl_xor_sync(0xffffffffu, v, 8);
    v += __shfl_xor_sync(0xffffffffu, v, 4);
    v += __shfl_xor_sync(0xffffffffu, v, 2);
    v += __shfl_xor_sync(0xffffffffu, v, 1);
    return v;
}

__device__ __forceinline__ float gelu_tanh(float x) {
    float x3 = x * x * x;
    return 0.5f * x * (1.0f + tanhf(0.7978845608028654f * (x + 0.044715f * x3)));
}

__device__ __forceinline__ uint32_t smem_u32(const void* p) {
    uint32_t a;
    asm("{ .reg .u64 t; cvta.to.shared.u64 t, %1; cvt.u32.u64 %0, t; }" : "=r"(a) : "l"(p));
    return a;
}

// fp32 -> (hi, lo) bf16 pair, packed two-at-a-time into b32 (a in low half)
__device__ __forceinline__ uint32_t split_pack(float a, float b, uint32_t& lo) {
    __nv_bfloat16 ha = __float2bfloat16(a), hb = __float2bfloat16(b);
    float ra = a - __bfloat162float(ha);
    float rb = b - __bfloat162float(hb);
    __nv_bfloat16 la = __float2bfloat16(ra), lb = __float2bfloat16(rb);
    lo = (uint32_t)__bfloat16_as_ushort(la) | ((uint32_t)__bfloat16_as_ushort(lb) << 16);
    return (uint32_t)__bfloat16_as_ushort(ha) | ((uint32_t)__bfloat16_as_ushort(hb) << 16);
}

__device__ __forceinline__ void split_store2(__nv_bfloat16* hi, __nv_bfloat16* lo,
                                             size_t idx, float a, float b) {
    __nv_bfloat16 ha = __float2bfloat16(a), hb = __float2bfloat16(b);
    __nv_bfloat162 hv; hv.x = ha; hv.y = hb;
    *(__nv_bfloat162*)&hi[idx] = hv;
    __nv_bfloat162 lv;
    lv.x = __float2bfloat16(a - __bfloat162float(ha));
    lv.y = __float2bfloat16(b - __bfloat162float(hb));
    *(__nv_bfloat162*)&lo[idx] = lv;
}

// ---------------- warp-level MMA primitives (sm_80+, no 'a' features) --------
__device__ __forceinline__ void ldsm4(uint32_t* r, uint32_t a) {
    asm volatile("ldmatrix.sync.aligned.m8n8.x4.shared.b16 {%0,%1,%2,%3}, [%4];"
        : "=r"(r[0]), "=r"(r[1]), "=r"(r[2]), "=r"(r[3]) : "r"(a));
}
__device__ __forceinline__ void ldsm4t(uint32_t* r, uint32_t a) {
    asm volatile("ldmatrix.sync.aligned.m8n8.x4.trans.shared.b16 {%0,%1,%2,%3}, [%4];"
        : "=r"(r[0]), "=r"(r[1]), "=r"(r[2]), "=r"(r[3]) : "r"(a));
}
__device__ __forceinline__ void mma16816(float* c, const uint32_t* a, const uint32_t* b) {
    asm volatile(
        "mma.sync.aligned.m16n8k16.row.col.f32.bf16.bf16.f32 "
        "{%0,%1,%2,%3}, {%4,%5,%6,%7}, {%8,%9}, {%0,%1,%2,%3};"
        : "+f"(c[0]), "+f"(c[1]), "+f"(c[2]), "+f"(c[3])
        : "r"(a[0]), "r"(a[1]), "r"(a[2]), "r"(a[3]), "r"(b[0]), "r"(b[1]));
}

__device__ __forceinline__ void cpa16(uint32_t s, const void* g) {
    asm volatile("cp.async.cg.shared.global [%0], [%1], 16;" :: "r"(s), "l"(g));
}
#define CP_COMMIT() asm volatile("cp.async.commit_group;" ::: "memory")
#define CP_WAIT1()  asm volatile("cp.async.wait_group 1;" ::: "memory")
#define CP_WAIT0()  asm volatile("cp.async.wait_group 0;" ::: "memory")

// ---------------- K-1: weight pre-split (fp32 -> bf16 hi/lo planes) ----------
__global__ void split_w(const float* __restrict__ W,
                        __nv_bfloat16* __restrict__ hi,
                        __nv_bfloat16* __restrict__ lo, int n4) {
    int i = blockIdx.x * 256 + threadIdx.x;
    if (i >= n4) return;
    float4 v = ((const float4*)W)[i];
    uint32_t l0, l1;
    uint32_t h0 = split_pack(v.x, v.y, l0);
    uint32_t h1 = split_pack(v.z, v.w, l1);
    ((uint2*)hi)[i] = make_uint2(h0, h1);
    ((uint2*)lo)[i] = make_uint2(l0, l1);
}

// ---------------- K0: adaLN modulation ---------------------------------------
__global__ void ada_kernel(const float* __restrict__ c,
                           const float* __restrict__ W,
                           const float* __restrict__ bias,
                           float* __restrict__ mod) {
    __shared__ float cs[BATCH * 1024];
    int tid = threadIdx.x;
    for (int i = tid; i < BATCH * 1024; i += 256) cs[i] = c[i];
    __syncthreads();
    int n = blockIdx.x * 256 + tid;
    float a0 = 0.f, a1 = 0.f, a2 = 0.f, a3 = 0.f;
    #pragma unroll 4
    for (int k = 0; k < 1024; k++) {
        float w = W[(size_t)k * MODW + n];
        a0 += cs[k] * w;
        a1 += cs[1024 + k] * w;
        a2 += cs[2048 + k] * w;
        a3 += cs[3072 + k] * w;
    }
    float bb = bias[n];
    mod[n] = a0 + bb;
    mod[MODW + n] = a1 + bb;
    mod[2 * MODW + n] = a2 + bb;
    mod[3 * MODW + n] = a3 + bb;
}

// ---------------- K1: LayerNorm + modulate -> split bf16 planes --------------
__global__ void ln_mod_kernel(const float* __restrict__ x,
                              const float* __restrict__ w,
                              const float* __restrict__ mod,
                              int shOff, int scOff,
                              __nv_bfloat16* __restrict__ ohi,
                              __nv_bfloat16* __restrict__ olo) {
    int token = blockIdx.x;
    int b = token >> 11;
    int tid = threadIdx.x;
    const float* xr = x + (size_t)token * DMODEL;
    float4 v = ((const float4*)xr)[tid];
    float lsum = v.x + v.y + v.z + v.w;
    float lsq = v.x * v.x + v.y * v.y + v.z * v.z + v.w * v.w;
    __shared__ float s1[8], s2[8];
    float ws = warpSum(lsum), wq = warpSum(lsq);
    int warp = tid >> 5, lane = tid & 31;
    if (lane == 0) { s1[warp] = ws; s2[warp] = wq; }
    __syncthreads();
    __shared__ float s_mu, s_rstd;
    if (tid == 0) {
        float ts = 0.f, tq = 0.f;
        #pragma unroll
        for (int i = 0; i < 8; i++) { ts += s1[i]; tq += s2[i]; }
        float mu = ts * (1.0f / DMODEL);
        float var = tq * (1.0f / DMODEL) - mu * mu;
        s_mu = mu;
        s_rstd = rsqrtf(var + 1e-5f);
    }
    __syncthreads();
    float mu = s_mu, rstd = s_rstd;
    const float* mrow = mod + (size_t)b * MODW;
    size_t rowoff = (size_t)token * DMODEL;
    int d = tid * 4;
    float4 wv = *(const float4*)&w[d];
    float4 sc = *(const float4*)&mrow[scOff + d];
    float4 sh = *(const float4*)&mrow[shOff + d];
    float o0 = (v.x - mu) * rstd * wv.x * (1.f + sc.x) + sh.x;
    float o1 = (v.y - mu) * rstd * wv.y * (1.f + sc.y) + sh.y;
    float o2 = (v.z - mu) * rstd * wv.z * (1.f + sc.z) + sh.z;
    float o3 = (v.w - mu) * rstd * wv.w * (1.f + sc.w) + sh.w;
    split_store2(ohi, olo, rowoff + d, o0, o1);
    split_store2(ohi, olo, rowoff + d + 2, o2, o3);
}

// ---------------- split-bf16 HMMA GEMM (R14-proven 2-stage) ------------------
#define AST    80
#define BSTB   272
#define A_LO_OFF 10240
#define B_HI_OFF 20480
#define STAGE  37888
#define GEMM_SMEM (2 * STAGE)   // 75776

template <int EPI>
__device__ __forceinline__ float epi_apply(float v, int m, int n, int N,
        const float* __restrict__ bias, const float* __restrict__ resid,
        const float* __restrict__ mod, int modOff) {
    if (EPI == 2) v = resid[(size_t)m * N + n]
                    + mod[(size_t)(m >> 11) * MODW + modOff + n] * v;
    if (EPI == 3) v = resid[(size_t)m * N + n]
                    + mod[(size_t)(m >> 11) * MODW + modOff + n] * (v + bias[n]);
    return v;
}

// EPI 1: Chi/Clo(bf16 split) = gelu(A@B + bias)
// EPI 2: C = resid + mod[b, modOff+n] * (A@B)              (N == 1024)
// EPI 3: C = resid + mod[b, modOff+n] * (A@B + bias)       (N == 1024)
template <int EPI>
__global__ void __launch_bounds__(256, 2)
mma_gemm(const __nv_bfloat16* __restrict__ Ahg, const __nv_bfloat16* __restrict__ Alg,
         const __nv_bfloat16* __restrict__ Bhg, const __nv_bfloat16* __restrict__ Blg,
         float* __restrict__ C,
         __nv_bfloat16* __restrict__ Chi, __nv_bfloat16* __restrict__ Clo,
         int M, int N, int K,
         const float* __restrict__ bias,
         const float* __restrict__ resid,
         const float* __restrict__ mod, int modOff) {
    extern __shared__ char smem[];
    uint32_t sb = smem_u32(smem);
    int tid = threadIdx.x, lane = tid & 31, wid = tid >> 5;
    int wm = wid >> 1, wn = wid & 1;
    int m0 = blockIdx.y * 128, n0 = blockIdx.x * 128;

    float acc[2][8][4];
    #pragma unroll
    for (int i = 0; i < 2; i++)
        #pragma unroll
        for (int j = 0; j < 8; j++)
            #pragma unroll
            for (int k = 0; k < 4; k++) acc[i][j][k] = 0.f;

    int s0 = tid * 2;
    int arow0 = s0 >> 2,  aoff0 = s0 & 3;
    int arow1 = (s0+1) >> 2, aoff1 = (s0+1) & 3;
    int brow0 = s0 >> 4,  boff0 = s0 & 15;
    int brow1 = (s0+1) >> 4, boff1 = (s0+1) & 15;

    uint32_t aBase = sb + (uint32_t)(wm * 32 + (lane & 15)) * AST + (uint32_t)((lane >> 4) * 8) * 2;
    int bg = lane >> 3;
    uint32_t bBase = sb + B_HI_OFF
                   + (uint32_t)((bg & 1) * 8 + (lane & 7)) * BSTB
                   + (uint32_t)(wn * 64 + ((bg >> 1) & 1) * 8) * 2;

    const int nc = K >> 5;

    auto load_stage = [&](int c, int st) {
        int k0 = c << 5;
        uint32_t sA = sb + st * STAGE;
        uint32_t sB = sA + B_HI_OFF;
        cpa16(sA + arow0 * AST + aoff0 * 16,
              Ahg + (size_t)(m0 + arow0) * K + k0 + aoff0 * 8);
        cpa16(sA + arow0 * AST + aoff0 * 16 + A_LO_OFF,
              Alg + (size_t)(m0 + arow0) * K + k0 + aoff0 * 8);
        cpa16(sA + arow1 * AST + aoff1 * 16,
              Ahg + (size_t)(m0 + arow1) * K + k0 + aoff1 * 8);
        cpa16(sA + arow1 * AST + aoff1 * 16 + A_LO_OFF,
              Alg + (size_t)(m0 + arow1) * K + k0 + aoff1 * 8);
        cpa16(sB + brow0 * BSTB + boff0 * 16,
              Bhg + (size_t)(k0 + brow0) * N + n0 + boff0 * 8);
        cpa16(sB + brow0 * BSTB + boff0 * 16 + 8704,
              Blg + (size_t)(k0 + brow0) * N + n0 + boff0 * 8);
        cpa16(sB + brow1 * BSTB + boff1 * 16,
              Bhg + (size_t)(k0 + brow1) * N + n0 + boff1 * 8);
        cpa16(sB + brow1 * BSTB + boff1 * 16 + 8704,
              Blg + (size_t)(k0 + brow1) * N + n0 + boff1 * 8);
    };

    load_stage(0, 0);
    CP_COMMIT();

    for (int c = 0; c < nc; c++) {
        if (c + 1 < nc) {
            load_stage(c + 1, (c + 1) & 1);
            CP_COMMIT();
            CP_WAIT1();
        } else {
            CP_WAIT0();
        }
        __syncthreads();

        uint32_t stOff = (uint32_t)(c & 1) * STAGE;
        #pragma unroll
        for (int ks = 0; ks < 2; ks++) {
            uint32_t ah[2][4], al[2][4];
            #pragma unroll
            for (int mt = 0; mt < 2; mt++) {
                ldsm4(ah[mt], aBase + stOff + mt * 16 * AST + ks * 32);
                ldsm4(al[mt], aBase + stOff + A_LO_OFF + mt * 16 * AST + ks * 32);
            }
            #pragma unroll
            for (int q = 0; q < 4; q++) {
                uint32_t bh[4], bl[4];
                ldsm4t(bh, bBase + stOff + q * 32 + ks * 16 * BSTB);
                ldsm4t(bl, bBase + stOff + 8704 + q * 32 + ks * 16 * BSTB);
                #pragma unroll
                for (int mt = 0; mt < 2; mt++) {
                    mma16816(acc[mt][2 * q],     ah[mt], bh);
                    mma16816(acc[mt][2 * q],     ah[mt], bl);
                    mma16816(acc[mt][2 * q],     al[mt], bh);
                    mma16816(acc[mt][2 * q + 1], ah[mt], bh + 2);
                    mma16816(acc[mt][2 * q + 1], ah[mt], bl + 2);
                    mma16816(acc[mt][2 * q + 1], al[mt], bh + 2);
                }
            }
        }
        __syncthreads();
    }

    int r0 = lane >> 2, cp2 = (lane & 3) * 2;
    #pragma unroll
    for (int mt = 0; mt < 2; mt++) {
        #pragma unroll
        for (int nt = 0; nt < 8; nt++) {
            int m = m0 + wm * 32 + mt * 16 + r0;
            int n = n0 + wn * 64 + nt * 8 + cp2;
            float* cacc = acc[mt][nt];
            if (EPI == 1) {
                float v00 = gelu_tanh(cacc[0] + bias[n]);
                float v01 = gelu_tanh(cacc[1] + bias[n + 1]);
                float v10 = gelu_tanh(cacc[2] + bias[n]);
                float v11 = gelu_tanh(cacc[3] + bias[n + 1]);
                split_store2(Chi, Clo, (size_t)m * N + n, v00, v01);
                split_store2(Chi, Clo, (size_t)(m + 8) * N + n, v10, v11);
            } else {
                float2 o0, o1;
                o0.x = epi_apply<EPI>(cacc[0], m, n,     N, bias, resid, mod, modOff);
                o0.y = epi_apply<EPI>(cacc[1], m, n + 1, N, bias, resid, mod, modOff);
                o1.x = epi_apply<EPI>(cacc[2], m + 8, n,     N, bias, resid, mod, modOff);
                o1.y = epi_apply<EPI>(cacc[3], m + 8, n + 1, N, bias, resid, mod, modOff);
                *(float2*)&C[(size_t)m * N + n] = o0;
                *(float2*)&C[(size_t)(m + 8) * N + n] = o1;
            }
        }
    }
}

// ---------------- K2: QKV GEMM + fused RMSNorm/RoPE/split (2-stage) ----------
// Each warp's 64 cols = exactly one (t, head): t = q/k/v. Outputs planes
// [B][H][S][HD]; q pre-scaled by 0.125*log2(e).
__global__ void __launch_bounds__(256, 2)
mma_gemm_qkv(const __nv_bfloat16* __restrict__ Ahg, const __nv_bfloat16* __restrict__ Alg,
             const __nv_bfloat16* __restrict__ Bhg, const __nv_bfloat16* __restrict__ Blg,
             const float* __restrict__ cosb, const float* __restrict__ sinb,
             const float* __restrict__ qw, const float* __restrict__ kw,
             __nv_bfloat16* __restrict__ qh, __nv_bfloat16* __restrict__ ql,
             __nv_bfloat16* __restrict__ kh, __nv_bfloat16* __restrict__ kl,
             __nv_bfloat16* __restrict__ vh, __nv_bfloat16* __restrict__ vl) {
    extern __shared__ char smem[];
    uint32_t sb = smem_u32(smem);
    int tid = threadIdx.x, lane = tid & 31, wid = tid >> 5;
    int wm = wid >> 1, wn = wid & 1;
    int m0 = blockIdx.y * 128, n0 = blockIdx.x * 128;
    const int K = DMODEL, N = 3 * DMODEL;

    float acc[2][8][4];
    #pragma unroll
    for (int i = 0; i < 2; i++)
        #pragma unroll
        for (int j = 0; j < 8; j++)
            #pragma unroll
            for (int k = 0; k < 4; k++) acc[i][j][k] = 0.f;

    int s0 = tid * 2;
    int arow0 = s0 >> 2,  aoff0 = s0 & 3;
    int arow1 = (s0+1) >> 2, aoff1 = (s0+1) & 3;
    int brow0 = s0 >> 4,  boff0 = s0 & 15;
    int brow1 = (s0+1) >> 4, boff1 = (s0+1) & 15;

    uint32_t aBase = sb + (uint32_t)(wm * 32 + (lane & 15)) * AST + (uint32_t)((lane >> 4) * 8) * 2;
    int bg = lane >> 3;
    uint32_t bBase = sb + B_HI_OFF
                   + (uint32_t)((bg & 1) * 8 + (lane & 7)) * BSTB
                   + (uint32_t)(wn * 64 + ((bg >> 1) & 1) * 8) * 2;

    const int nc = K >> 5;

    auto load_stage = [&](int c, int st) {
        int k0 = c << 5;
        uint32_t sA = sb + st * STAGE;
        uint32_t sB = sA + B_HI_OFF;
        cpa16(sA + arow0 * AST + aoff0 * 16,
              Ahg + (size_t)(m0 + arow0) * K + k0 + aoff0 * 8);
        cpa16(sA + arow0 * AST + aoff0 * 16 + A_LO_OFF,
              Alg + (size_t)(m0 + arow0) * K + k0 + aoff0 * 8);
        cpa16(sA + arow1 * AST + aoff1 * 16,
              Ahg + (size_t)(m0 + arow1) * K + k0 + aoff1 * 8);
        cpa16(sA + arow1 * AST + aoff1 * 16 + A_LO_OFF,
              Alg + (size_t)(m0 + arow1) * K + k0 + aoff1 * 8);
        cpa16(sB + brow0 * BSTB + boff0 * 16,
              Bhg + (size_t)(k0 + brow0) * N + n0 + boff0 * 8);
        cpa16(sB + brow0 * BSTB + boff0 * 16 + 8704,
              Blg + (size_t)(k0 + brow0) * N + n0 + boff0 * 8);
        cpa16(sB + brow1 * BSTB + boff1 * 16,
              Bhg + (size_t)(k0 + brow1) * N + n0 + boff1 * 8);
        cpa16(sB + brow1 * BSTB + boff1 * 16 + 8704,
              Blg + (size_t)(k0 + brow1) * N + n0 + boff1 * 8);
    };

    load_stage(0, 0);
    CP_COMMIT();

    for (int c = 0; c < nc; c++) {
        if (c + 1 < nc) {
            load_stage(c + 1, (c + 1) & 1);
            CP_COMMIT();
            CP_WAIT1();
        } else {
            CP_WAIT0();
        }
        __syncthreads();

        uint32_t stOff = (uint32_t)(c & 1) * STAGE;
        #pragma unroll
        for (int ks = 0; ks < 2; ks++) {
            uint32_t ah[2][4], al[2][4];
            #pragma unroll
            for (int mt = 0; mt < 2; mt++) {
                ldsm4(ah[mt], aBase + stOff + mt * 16 * AST + ks * 32);
                ldsm4(al[mt], aBase + stOff + A_LO_OFF + mt * 16 * AST + ks * 32);
            }
            #pragma unroll
            for (int q = 0; q < 4; q++) {
                uint32_t bh[4], bl[4];
                ldsm4t(bh, bBase + stOff + q * 32 + ks * 16 * BSTB);
                ldsm4t(bl, bBase + stOff + 8704 + q * 32 + ks * 16 * BSTB);
                #pragma unroll
                for (int mt = 0; mt < 2; mt++) {
                    mma16816(acc[mt][2 * q],     ah[mt], bh);
                    mma16816(acc[mt][2 * q],     ah[mt], bl);
                    mma16816(acc[mt][2 * q],     al[mt], bh);
                    mma16816(acc[mt][2 * q + 1], ah[mt], bh + 2);
                    mma16816(acc[mt][2 * q + 1], ah[mt], bl + 2);
                    mma16816(acc[mt][2 * q + 1], al[mt], bh + 2);
                }
            }
        }
        __syncthreads();
    }

    // ---- fused epilogue: RMSNorm + RoPE + split (validated in R15) ----
    int r0 = lane >> 2, cp2 = (lane & 3) * 2;
    int nw = n0 + wn * 64;
    int t = nw >> 10;                 // 0=q 1=k 2=v
    int hh = (nw >> 6) & 15;          // head
    #pragma unroll
    for (int mt = 0; mt < 2; mt++) {
        int mA = m0 + wm * 32 + mt * 16 + r0;
        int mB = mA + 8;
        int sA = mA & (SEQ - 1), sB2 = mB & (SEQ - 1);
        size_t baseA = (((size_t)((mA >> 11) * NHEAD + hh)) * SEQ + sA) * HDIM;
        size_t baseB = (((size_t)((mB >> 11) * NHEAD + hh)) * SEQ + sB2) * HDIM;
        if (t == 2) {
            #pragma unroll
            for (int nt = 0; nt < 8; nt++) {
                int d = nt * 8 + cp2;
                split_store2(vh, vl, baseA + d, acc[mt][nt][0], acc[mt][nt][1]);
                split_store2(vh, vl, baseB + d, acc[mt][nt][2], acc[mt][nt][3]);
            }
        } else {
            const float* w = (t == 0) ? qw : kw;
            float ss0 = 0.f, ss1 = 0.f;
            #pragma unroll
            for (int nt = 0; nt < 8; nt++) {
                ss0 += acc[mt][nt][0] * acc[mt][nt][0] + acc[mt][nt][1] * acc[mt][nt][1];
                ss1 += acc[mt][nt][2] * acc[mt][nt][2] + acc[mt][nt][3] * acc[mt][nt][3];
            }
            ss0 += __shfl_xor_sync(0xffffffffu, ss0, 1);
            ss0 += __shfl_xor_sync(0xffffffffu, ss0, 2);
            ss1 += __shfl_xor_sync(0xffffffffu, ss1, 1);
            ss1 += __shfl_xor_sync(0xffffffffu, ss1, 2);
            float ri0 = rsqrtf(ss0 * (1.0f / HDIM) + 1e-6f);
            float ri1 = rsqrtf(ss1 * (1.0f / HDIM) + 1e-6f);
            float xa[16], xb[16];
            #pragma unroll
            for (int nt = 0; nt < 8; nt++) {
                int d = nt * 8 + cp2;
                float w0 = w[d], w1 = w[d + 1];
                xa[2 * nt]     = acc[mt][nt][0] * ri0 * w0;
                xa[2 * nt + 1] = acc[mt][nt][1] * ri0 * w1;
                xb[2 * nt]     = acc[mt][nt][2] * ri1 * w0;
                xb[2 * nt + 1] = acc[mt][nt][3] * ri1 * w1;
            }
            const float SC = (t == 0) ? 0.125f * 1.4426950408889634f : 1.0f;
            __nv_bfloat16* oh = (t == 0) ? qh : kh;
            __nv_bfloat16* ol = (t == 0) ? ql : kl;
            #pragma unroll
            for (int nt = 0; nt < 8; nt++) {
                int d = nt * 8 + cp2;
                int p = nt ^ 4;
                float sg = (nt < 4) ? -1.f : 1.f;
                float2 cA = *(const float2*)&cosb[sA * HDIM + d];
                float2 sAv = *(const float2*)&sinb[sA * HDIM + d];
                float2 cB = *(const float2*)&cosb[sB2 * HDIM + d];
                float2 sBv = *(const float2*)&sinb[sB2 * HDIM + d];
                float oA0 = (xa[2 * nt] * cA.x + sg * xa[2 * p] * sAv.x) * SC;
                float oA1 = (xa[2 * nt + 1] * cA.y + sg * xa[2 * p + 1] * sAv.y) * SC;
                float oB0 = (xb[2 * nt] * cB.x + sg * xb[2 * p] * sBv.x) * SC;
                float oB1 = (xb[2 * nt + 1] * cB.y + sg * xb[2 * p + 1] * sBv.y) * SC;
                split_store2(oh, ol, baseA + d, oA0, oA1);
                split_store2(oh, ol, baseB + d, oB0, oB1);
            }
        }
    }
}

// ---------------- K4: HMMA flash attention (R14-proven 2-stage) --------------
#define FST   144
#define FSTAGE 36864
#define FLASH_SMEM (2 * FSTAGE)   // 73728

__global__ void __launch_bounds__(256, 2)
flash_mma(const __nv_bfloat16* __restrict__ qh, const __nv_bfloat16* __restrict__ ql,
          const __nv_bfloat16* __restrict__ kh, const __nv_bfloat16* __restrict__ kl,
          const __nv_bfloat16* __restrict__ vh, const __nv_bfloat16* __restrict__ vl,
          __nv_bfloat16* __restrict__ ohi, __nv_bfloat16* __restrict__ olo) {
    extern __shared__ char smem[];
    uint32_t sb = smem_u32(smem);
    int tid = threadIdx.x, lane = tid & 31, wid = tid >> 5;
    int bhid = blockIdx.x;               // b*16 + h
    int h = bhid & 15, b = bhid >> 4;
    int q0 = blockIdx.y * 128;
    size_t hoff = (size_t)bhid * SEQ * HDIM;

    // ---- Q -> smem (stage0 region) -> registers ----
    #pragma unroll
    for (int i = 0; i < 4; i++) {
        int c = tid + i * 256;
        int row = c >> 3, col = c & 7;
        cpa16(sb + row * FST + col * 16, qh + hoff + (size_t)(q0 + row) * HDIM + col * 8);
        cpa16(sb + 18432 + row * FST + col * 16, ql + hoff + (size_t)(q0 + row) * HDIM + col * 8);
    }
    CP_COMMIT(); CP_WAIT0();
    __syncthreads();
    uint32_t qfh[4][4], qfl[4][4];
    {
        uint32_t aB = sb + (uint32_t)(wid * 16 + (lane & 15)) * FST + (uint32_t)((lane >> 4) * 16);
        #pragma unroll
        for (int kt = 0; kt < 4; kt++) {
            ldsm4(qfh[kt], aB + kt * 32);
            ldsm4(qfl[kt], aB + 18432 + kt * 32);
        }
    }
    __syncthreads();

    float o[8][4];
    #pragma unroll
    for (int i = 0; i < 8; i++)
        #pragma unroll
        for (int j = 0; j < 4; j++) o[i][j] = 0.f;
    float m0 = -1e30f, m1 = -1e30f, l0 = 0.f, l1 = 0.f;

    uint32_t kB = (uint32_t)((lane & 7) + ((lane >> 4) << 3)) * FST + (uint32_t)(((lane >> 3) & 1) << 4);
    int bg = lane >> 3;
    uint32_t vB = (uint32_t)((bg & 1) * 8 + (lane & 7)) * FST + (uint32_t)(((bg >> 1)) << 4);

    auto load_kv = [&](int t, int st) {
        int k0 = t * 64;
        uint32_t sbase = sb + st * FSTAGE;
        #pragma unroll
        for (int i = 0; i < 2; i++) {
            int c = tid + i * 256;
            int row = c >> 3, col = c & 7;
            size_t goff = hoff + (size_t)(k0 + row) * HDIM + col * 8;
            uint32_t d = sbase + row * FST + col * 16;
            cpa16(d, kh + goff);
            cpa16(d + 9216, kl + goff);
            cpa16(d + 18432, vh + goff);
            cpa16(d + 27648, vl + goff);
        }
    };

    load_kv(0, 0);
    CP_COMMIT();

    const int NT = SEQ / 64;
    for (int t = 0; t < NT; t++) {
        if (t + 1 < NT) {
            load_kv(t + 1, (t + 1) & 1);
            CP_COMMIT();
            CP_WAIT1();
        } else {
            CP_WAIT0();
        }
        __syncthreads();
        uint32_t stB = sb + (uint32_t)(t & 1) * FSTAGE;

        // ---- S = Q K^T (split, 3 passes) ----
        float s[8][4];
        #pragma unroll
        for (int i = 0; i < 8; i++)
            #pragma unroll
            for (int j = 0; j < 4; j++) s[i][j] = 0.f;
        #pragma unroll
        for (int kt = 0; kt < 4; kt++) {
            #pragma unroll
            for (int kg = 0; kg < 4; kg++) {
                uint32_t fh[4], fl[4];
                uint32_t addr = stB + kB + kg * (16 * FST) + kt * 32;
                ldsm4(fh, addr);
                ldsm4(fl, addr + 9216);
                mma16816(s[kg * 2],     qfh[kt], fh);
                mma16816(s[kg * 2],     qfh[kt], fl);
                mma16816(s[kg * 2],     qfl[kt], fh);
                mma16816(s[kg * 2 + 1], qfh[kt], fh + 2);
                mma16816(s[kg * 2 + 1], qfh[kt], fl + 2);
                mma16816(s[kg * 2 + 1], qfl[kt], fh + 2);
            }
        }

        // ---- online softmax (base-2; scale folded into Q) ----
        float tm0 = -1e30f, tm1 = -1e30f;
        #pragma unroll
        for (int i = 0; i < 8; i++) {
            tm0 = fmaxf(tm0, fmaxf(s[i][0], s[i][1]));
            tm1 = fmaxf(tm1, fmaxf(s[i][2], s[i][3]));
        }
        tm0 = fmaxf(tm0, __shfl_xor_sync(0xffffffffu, tm0, 1));
        tm0 = fmaxf(tm0, __shfl_xor_sync(0xffffffffu, tm0, 2));
        tm1 = fmaxf(tm1, __shfl_xor_sync(0xffffffffu, tm1, 1));
        tm1 = fmaxf(tm1, __shfl_xor_sync(0xffffffffu, tm1, 2));
        float mn0 = fmaxf(m0, tm0), mn1 = fmaxf(m1, tm1);
        float al0 = exp2f(m0 - mn0), al1 = exp2f(m1 - mn1);
        float ts0 = 0.f, ts1 = 0.f;
        #pragma unroll
        for (int i = 0; i < 8; i++) {
            s[i][0] = exp2f(s[i][0] - mn0);
            s[i][1] = exp2f(s[i][1] - mn0);
            s[i][2] = exp2f(s[i][2] - mn1);
            s[i][3] = exp2f(s[i][3] - mn1);
            ts0 += s[i][0] + s[i][1];
            ts1 += s[i][2] + s[i][3];
        }
        ts0 += __shfl_xor_sync(0xffffffffu, ts0, 1);
        ts0 += __shfl_xor_sync(0xffffffffu, ts0, 2);
        ts1 += __shfl_xor_sync(0xffffffffu, ts1, 1);
        ts1 += __shfl_xor_sync(0xffffffffu, ts1, 2);
        l0 = l0 * al0 + ts0;
        l1 = l1 * al1 + ts1;
        m0 = mn0; m1 = mn1;
        #pragma unroll
        for (int i = 0; i < 8; i++) {
            o[i][0] *= al0; o[i][1] *= al0;
            o[i][2] *= al1; o[i][3] *= al1;
        }

        // ---- O += P V (split P in-register, split V, 3 passes) ----
        #pragma unroll
        for (int kt2 = 0; kt2 < 4; kt2++) {
            uint32_t ph[4], pl[4];
            ph[0] = split_pack(s[kt2 * 2][0],     s[kt2 * 2][1],     pl[0]);
            ph[1] = split_pack(s[kt2 * 2][2],     s[kt2 * 2][3],     pl[1]);
            ph[2] = split_pack(s[kt2 * 2 + 1][0], s[kt2 * 2 + 1][1], pl[2]);
            ph[3] = split_pack(s[kt2 * 2 + 1][2], s[kt2 * 2 + 1][3], pl[3]);
            #pragma unroll
            for (int nq = 0; nq < 4; nq++) {
                uint32_t wh[4], wl[4];
                uint32_t addr = stB + 18432 + vB + kt2 * (16 * FST) + nq * 32;
                ldsm4t(wh, addr);
                ldsm4t(wl, addr + 9216);
                mma16816(o[nq * 2],     ph, wh);
                mma16816(o[nq * 2],     pl, wh);
                mma16816(o[nq * 2],     ph, wl);
                mma16816(o[nq * 2 + 1], ph, wh + 2);
                mma16816(o[nq * 2 + 1], pl, wh + 2);
                mma16816(o[nq * 2 + 1], ph, wl + 2);
            }
        }
        __syncthreads();
    }

    // ---- normalize + split store to attn planes [token][D] ----
    float inv0 = 1.f / l0, inv1 = 1.f / l1;
    int r0 = lane >> 2, cp2 = (lane & 3) * 2;
    int row0 = q0 + wid * 16 + r0;
    size_t t0 = (size_t)(b * SEQ + row0) * DMODEL + h * HDIM;
    size_t t1 = t0 + 8 * DMODEL;
    #pragma unroll
    for (int nt = 0; nt < 8; nt++) {
        split_store2(ohi, olo, t0 + nt * 8 + cp2, o[nt][0] * inv0, o[nt][1] * inv0);
        split_store2(ohi, olo, t1 + nt * 8 + cp2, o[nt][2] * inv1, o[nt][3] * inv1);
    }
}

// ---------------- launcher ---------------------------------------------------
extern "C" void kernel_launch(void* const* d_in, const int* in_sizes, int n_in,
                              void* d_out, int out_size) {
    const float* x       = (const float*)d_in[0];
    const float* cosb    = (const float*)d_in[1];
    const float* sinb    = (const float*)d_in[2];
    const float* c       = (const float*)d_in[3];
    const float* norm1_w = (const float*)d_in[4];
    const float* Wqkv    = (const float*)d_in[5];
    const float* Wout    = (const float*)d_in[6];
    const float* q_norm_w= (const float*)d_in[7];
    const float* k_norm_w= (const float*)d_in[8];
    const float* norm2_w = (const float*)d_in[9];
    const float* W1      = (const float*)d_in[10];
    const float* b1      = (const float*)d_in[11];
    const float* W2      = (const float*)d_in[12];
    const float* b2      = (const float*)d_in[13];
    const float* ada_W   = (const float*)d_in[14];
    const float* ada_b   = (const float*)d_in[15];
    float* out = (float*)d_out;

    float *mod_p;
    __nv_bfloat16 *xnh, *xnl, *ath, *atl, *hh, *hl;
    __nv_bfloat16 *wqh, *wql, *woh, *wol, *w1h, *w1l, *w2h, *w2l;
    __nv_bfloat16 *qph, *qpl, *kph, *kpl, *vph, *vpl;
    cudaGetSymbolAddress((void**)&mod_p, g_mod);
    cudaGetSymbolAddress((void**)&xnh, g_xn_hi);
    cudaGetSymbolAddress((void**)&xnl, g_xn_lo);
    cudaGetSymbolAddress((void**)&ath, g_attn_hi);
    cudaGetSymbolAddress((void**)&atl, g_attn_lo);
    cudaGetSymbolAddress((void**)&hh, g_h_hi);
    cudaGetSymbolAddress((void**)&hl, g_h_lo);
    cudaGetSymbolAddress((void**)&wqh, g_wqkv_hi);
    cudaGetSymbolAddress((void**)&wql, g_wqkv_lo);
    cudaGetSymbolAddress((void**)&woh, g_wout_hi);
    cudaGetSymbolAddress((void**)&wol, g_wout_lo);
    cudaGetSymbolAddress((void**)&w1h, g_w1_hi);
    cudaGetSymbolAddress((void**)&w1l, g_w1_lo);
    cudaGetSymbolAddress((void**)&w2h, g_w2_hi);
    cudaGetSymbolAddress((void**)&w2l, g_w2_lo);
    cudaGetSymbolAddress((void**)&qph, g_q_hi);
    cudaGetSymbolAddress((void**)&qpl, g_q_lo);
    cudaGetSymbolAddress((void**)&kph, g_k_hi);
    cudaGetSymbolAddress((void**)&kpl, g_k_lo);
    cudaGetSymbolAddress((void**)&vph, g_v_hi);
    cudaGetSymbolAddress((void**)&vpl, g_v_lo);

    cudaFuncSetAttribute(mma_gemm<1>, cudaFuncAttributeMaxDynamicSharedMemorySize, GEMM_SMEM);
    cudaFuncSetAttribute(mma_gemm<2>, cudaFuncAttributeMaxDynamicSharedMemorySize, GEMM_SMEM);
    cudaFuncSetAttribute(mma_gemm<3>, cudaFuncAttributeMaxDynamicSharedMemorySize, GEMM_SMEM);
    cudaFuncSetAttribute(mma_gemm_qkv, cudaFuncAttributeMaxDynamicSharedMemorySize, GEMM_SMEM);
    cudaFuncSetAttribute(flash_mma, cudaFuncAttributeMaxDynamicSharedMemorySize, FLASH_SMEM);

    // weight pre-split
    split_w<<<(DMODEL*3*DMODEL/4)/256, 256>>>(Wqkv, wqh, wql, DMODEL*3*DMODEL/4);
    split_w<<<(DMODEL*DMODEL/4)/256, 256>>>(Wout, woh, wol, DMODEL*DMODEL/4);
    split_w<<<(DMODEL*DFF/4)/256, 256>>>(W1, w1h, w1l, DMODEL*DFF/4);
    split_w<<<(DFF*DMODEL/4)/256, 256>>>(W2, w2h, w2l, DFF*DMODEL/4);

    // K0: modulation
    ada_kernel<<<MODW / 256, 256>>>(c, ada_W, ada_b, mod_p);

    // K1: LN1 + modulate -> xn split planes
    ln_mod_kernel<<<TOKENS, 256>>>(x, norm1_w, mod_p, 0, 1024, xnh, xnl);

    // K2: QKV GEMM + fused RMSNorm/RoPE/split -> q/k/v planes [B][H][S][HD]
    mma_gemm_qkv<<<dim3(3 * DMODEL / 128, TOKENS / 128), 256, GEMM_SMEM>>>(
        xnh, xnl, wqh, wql, cosb, sinb, q_norm_w, k_norm_w,
        qph, qpl, kph, kpl, vph, vpl);

    // K4: HMMA flash attention -> attn split planes
    flash_mma<<<dim3(BATCH * NHEAD, SEQ / 128), 256, FLASH_SMEM>>>(
        qph, qpl, kph, kpl, vph, vpl, ath, atl);

    // K5: Wout GEMM + gated residual (g_msa @2048) -> out fp32
    mma_gemm<2><<<dim3(DMODEL / 128, TOKENS / 128), 256, GEMM_SMEM>>>(
        ath, atl, woh, wol, out, nullptr, nullptr,
        TOKENS, DMODEL, DMODEL, nullptr, x, mod_p, 2048);

    // K6: LN2 + modulate -> xn split planes
    ln_mod_kernel<<<TOKENS, 256>>>(out, norm2_w, mod_p, 3072, 4096, xnh, xnl);

    // K7: MLP up GEMM + bias + gelu -> h split planes
    mma_gemm<1><<<dim3(DFF / 128, TOKENS / 128), 256, GEMM_SMEM>>>(
        xnh, xnl, w1h, w1l, nullptr, hh, hl,
        TOKENS, DFF, DMODEL, b1, nullptr, nullptr, 0);

    // K8: MLP down GEMM + bias + gated residual (g_mlp @5120), in-place on out
    mma_gemm<3><<<dim3(DMODEL / 128, TOKENS / 128), 256, GEMM_SMEM>>>(
        hh, hl, w2h, w2l, out, nullptr, nullptr,
        TOKENS, DMODEL, DFF, b2, out, mod_p, 5120);
}

// round 17
// speedup vs baseline: 1.9525x; 1.2752x over previous
#include <cuda_runtime.h>
#include <cuda_bf16.h>
#include <math.h>
#include <stdint.h>

// Problem constants
#define BATCH 4
#define SEQ   2048
#define DMODEL 1024
#define NHEAD 16
#define HDIM  64
#define DFF   4096
#define TOKENS (BATCH*SEQ)       // 8192
#define MODW  6144               // 6*D

// ---------------- scratch (device globals; no allocations allowed) ----------
__device__ float g_mod[BATCH * MODW];
__device__ float g_xn[(size_t)TOKENS * DMODEL];        // tf32-rounded fp32
__device__ float g_attn[(size_t)TOKENS * DMODEL];      // tf32-rounded fp32
__device__ float g_h[(size_t)TOKENS * DFF];            // tf32-rounded fp32
// transposed + tf32-rounded weights, layout [N][K]
__device__ float g_wqkv_t[(size_t)3 * DMODEL * DMODEL];
__device__ float g_wout_t[(size_t)DMODEL * DMODEL];
__device__ float g_w1_t[(size_t)DFF * DMODEL];
__device__ float g_w2_t[(size_t)DMODEL * DFF];
// attention operand planes, layout [B][H][S][HD]
__device__ float g_q[(size_t)TOKENS * DMODEL];          // tf32-rounded fp32
__device__ float g_k[(size_t)TOKENS * DMODEL];          // tf32-rounded fp32
__device__ __nv_bfloat16 g_v_hi[(size_t)TOKENS * DMODEL];
__device__ __nv_bfloat16 g_v_lo[(size_t)TOKENS * DMODEL];

// ---------------- generic helpers -------------------------------------------
__device__ __forceinline__ float warpSum(float v) {
    v += __shfl_xor_sync(0xffffffffu, v, 16);
    v += __shfl_xor_sync(0xffffffffu, v, 8);
    v += __shfl_xor_sync(0xffffffffu, v, 4);
    v += __shfl_xor_sync(0xffffffffu, v, 2);
    v += __shfl_xor_sync(0xffffffffu, v, 1);
    return v;
}

__device__ __forceinline__ float gelu_tanh(float x) {
    float x3 = x * x * x;
    return 0.5f * x * (1.0f + tanhf(0.7978845608028654f * (x + 0.044715f * x3)));
}

__device__ __forceinline__ uint32_t smem_u32(const void* p) {
    uint32_t a;
    asm("{ .reg .u64 t; cvta.to.shared.u64 t, %1; cvt.u32.u64 %0, t; }" : "=r"(a) : "l"(p));
    return a;
}

__device__ __forceinline__ float to_tf32(float x) {
    uint32_t o, i = __float_as_uint(x);
    asm("cvt.rna.tf32.f32 %0, %1;" : "=r"(o) : "r"(i));
    return __uint_as_float(o);
}

// fp32 -> (hi, lo) bf16 pair, packed two-at-a-time into b32 (a in low half)
__device__ __forceinline__ uint32_t split_pack(float a, float b, uint32_t& lo) {
    __nv_bfloat16 ha = __float2bfloat16(a), hb = __float2bfloat16(b);
    float ra = a - __bfloat162float(ha);
    float rb = b - __bfloat162float(hb);
    __nv_bfloat16 la = __float2bfloat16(ra), lb = __float2bfloat16(rb);
    lo = (uint32_t)__bfloat16_as_ushort(la) | ((uint32_t)__bfloat16_as_ushort(lb) << 16);
    return (uint32_t)__bfloat16_as_ushort(ha) | ((uint32_t)__bfloat16_as_ushort(hb) << 16);
}

__device__ __forceinline__ void split_store2(__nv_bfloat16* hi, __nv_bfloat16* lo,
                                             size_t idx, float a, float b) {
    __nv_bfloat16 ha = __float2bfloat16(a), hb = __float2bfloat16(b);
    __nv_bfloat162 hv; hv.x = ha; hv.y = hb;
    *(__nv_bfloat162*)&hi[idx] = hv;
    __nv_bfloat162 lv;
    lv.x = __float2bfloat16(a - __bfloat162float(ha));
    lv.y = __float2bfloat16(b - __bfloat162float(hb));
    *(__nv_bfloat162*)&lo[idx] = lv;
}

// ---------------- warp-level MMA primitives (sm_80+, no 'a' features) --------
__device__ __forceinline__ void ldsm4(uint32_t* r, uint32_t a) {
    asm volatile("ldmatrix.sync.aligned.m8n8.x4.shared.b16 {%0,%1,%2,%3}, [%4];"
        : "=r"(r[0]), "=r"(r[1]), "=r"(r[2]), "=r"(r[3]) : "r"(a));
}
__device__ __forceinline__ void ldsm4t(uint32_t* r, uint32_t a) {
    asm volatile("ldmatrix.sync.aligned.m8n8.x4.trans.shared.b16 {%0,%1,%2,%3}, [%4];"
        : "=r"(r[0]), "=r"(r[1]), "=r"(r[2]), "=r"(r[3]) : "r"(a));
}
__device__ __forceinline__ void mma16816(float* c, const uint32_t* a, const uint32_t* b) {
    asm volatile(
        "mma.sync.aligned.m16n8k16.row.col.f32.bf16.bf16.f32 "
        "{%0,%1,%2,%3}, {%4,%5,%6,%7}, {%8,%9}, {%0,%1,%2,%3};"
        : "+f"(c[0]), "+f"(c[1]), "+f"(c[2]), "+f"(c[3])
        : "r"(a[0]), "r"(a[1]), "r"(a[2]), "r"(a[3]), "r"(b[0]), "r"(b[1]));
}
__device__ __forceinline__ void mma_tf32(float* c, const uint32_t* a, uint32_t b0, uint32_t b1) {
    asm volatile(
        "mma.sync.aligned.m16n8k8.row.col.f32.tf32.tf32.f32 "
        "{%0,%1,%2,%3}, {%4,%5,%6,%7}, {%8,%9}, {%0,%1,%2,%3};"
        : "+f"(c[0]), "+f"(c[1]), "+f"(c[2]), "+f"(c[3])
        : "r"(a[0]), "r"(a[1]), "r"(a[2]), "r"(a[3]), "r"(b0), "r"(b1));
}

__device__ __forceinline__ void cpa16(uint32_t s, const void* g) {
    asm volatile("cp.async.cg.shared.global [%0], [%1], 16;" :: "r"(s), "l"(g));
}
#define CP_COMMIT() asm volatile("cp.async.commit_group;" ::: "memory")
#define CP_WAIT1()  asm volatile("cp.async.wait_group 1;" ::: "memory")
#define CP_WAIT0()  asm volatile("cp.async.wait_group 0;" ::: "memory")

// ---------------- K-1: weight transpose + tf32 round: Wt[n][k] ---------------
__global__ void transp_w(const float* __restrict__ W, float* __restrict__ Wt,
                         int K, int N) {
    __shared__ float t[32][33];
    int n0 = blockIdx.x * 32, k0 = blockIdx.y * 32;
    int tx = threadIdx.x & 31, ty = threadIdx.x >> 5;   // 256 threads: ty 0..7
    #pragma unroll
    for (int i = 0; i < 32; i += 8)
        t[ty + i][tx] = W[(size_t)(k0 + ty + i) * N + n0 + tx];
    __syncthreads();
    #pragma unroll
    for (int i = 0; i < 32; i += 8)
        Wt[(size_t)(n0 + ty + i) * K + k0 + tx] = to_tf32(t[tx][ty + i]);
}

// ---------------- K0: adaLN modulation ---------------------------------------
__global__ void ada_kernel(const float* __restrict__ c,
                           const float* __restrict__ W,
                           const float* __restrict__ bias,
                           float* __restrict__ mod) {
    __shared__ float cs[BATCH * 1024];
    int tid = threadIdx.x;
    for (int i = tid; i < BATCH * 1024; i += 256) cs[i] = c[i];
    __syncthreads();
    int n = blockIdx.x * 256 + tid;
    float a0 = 0.f, a1 = 0.f, a2 = 0.f, a3 = 0.f;
    #pragma unroll 4
    for (int k = 0; k < 1024; k++) {
        float w = W[(size_t)k * MODW + n];
        a0 += cs[k] * w;
        a1 += cs[1024 + k] * w;
        a2 += cs[2048 + k] * w;
        a3 += cs[3072 + k] * w;
    }
    float bb = bias[n];
    mod[n] = a0 + bb;
    mod[MODW + n] = a1 + bb;
    mod[2 * MODW + n] = a2 + bb;
    mod[3 * MODW + n] = a3 + bb;
}

// ---------------- K1: LayerNorm + modulate -> tf32-rounded fp32 plane --------
__global__ void ln_mod_kernel(const float* __restrict__ x,
                              const float* __restrict__ w,
                              const float* __restrict__ mod,
                              int shOff, int scOff,
                              float* __restrict__ o) {
    int token = blockIdx.x;
    int b = token >> 11;
    int tid = threadIdx.x;
    const float* xr = x + (size_t)token * DMODEL;
    float4 v = ((const float4*)xr)[tid];
    float lsum = v.x + v.y + v.z + v.w;
    float lsq = v.x * v.x + v.y * v.y + v.z * v.z + v.w * v.w;
    __shared__ float s1[8], s2[8];
    float ws = warpSum(lsum), wq = warpSum(lsq);
    int warp = tid >> 5, lane = tid & 31;
    if (lane == 0) { s1[warp] = ws; s2[warp] = wq; }
    __syncthreads();
    __shared__ float s_mu, s_rstd;
    if (tid == 0) {
        float ts = 0.f, tq = 0.f;
        #pragma unroll
        for (int i = 0; i < 8; i++) { ts += s1[i]; tq += s2[i]; }
        float mu = ts * (1.0f / DMODEL);
        float var = tq * (1.0f / DMODEL) - mu * mu;
        s_mu = mu;
        s_rstd = rsqrtf(var + 1e-5f);
    }
    __syncthreads();
    float mu = s_mu, rstd = s_rstd;
    const float* mrow = mod + (size_t)b * MODW;
    int d = tid * 4;
    float4 wv = *(const float4*)&w[d];
    float4 sc = *(const float4*)&mrow[scOff + d];
    float4 sh = *(const float4*)&mrow[shOff + d];
    float4 ov;
    ov.x = to_tf32((v.x - mu) * rstd * wv.x * (1.f + sc.x) + sh.x);
    ov.y = to_tf32((v.y - mu) * rstd * wv.y * (1.f + sc.y) + sh.y);
    ov.z = to_tf32((v.z - mu) * rstd * wv.z * (1.f + sc.z) + sh.z);
    ov.w = to_tf32((v.w - mu) * rstd * wv.w * (1.f + sc.w) + sh.w);
    *(float4*)&o[(size_t)token * DMODEL + d] = ov;
}

// ---------------- TF32 HMMA GEMM, 128x128 tile, K-chunk 32, 2-stage ----------
// Stage layout (bytes):
//   A [128 rows x 32 fp32, stride 144]  @ 0       18432
//   B [128 n-rows x 32 fp32, stride 144]@ 18432   18432   (Bt is [N][K] in gmem)
#define ASTF  144
#define B_OFF 18432
#define STAGE 36864
#define GEMM_SMEM (2 * STAGE)   // 73728

template <int EPI>
__device__ __forceinline__ float epi_apply(float v, int m, int n, int N,
        const float* __restrict__ bias, const float* __restrict__ resid,
        const float* __restrict__ mod, int modOff) {
    if (EPI == 2) v = resid[(size_t)m * N + n]
                    + mod[(size_t)(m >> 11) * MODW + modOff + n] * v;
    if (EPI == 3) v = resid[(size_t)m * N + n]
                    + mod[(size_t)(m >> 11) * MODW + modOff + n] * (v + bias[n]);
    return v;
}

// shared mainloop: leaves acc[2][8][4]; call inside kernel after m0/n0 set
#define TF32_MAINLOOP(Ag, Bt, K)                                                   \
    float acc[2][8][4];                                                            \
    _Pragma("unroll")                                                              \
    for (int i = 0; i < 2; i++)                                                    \
        _Pragma("unroll")                                                          \
        for (int j = 0; j < 8; j++)                                                \
            _Pragma("unroll")                                                      \
            for (int k = 0; k < 4; k++) acc[i][j][k] = 0.f;                        \
    uint32_t aBase = sb + (uint32_t)(wm * 32 + (lane & 15)) * ASTF                 \
                   + (uint32_t)((lane >> 4)) * 16;                                 \
    uint32_t bBase = sb + B_OFF + (uint32_t)(wn * 64 + (lane & 15)) * ASTF         \
                   + (uint32_t)((lane >> 4)) * 16;                                 \
    const int nc = (K) >> 5;                                                       \
    auto load_stage = [&](int c, int st) {                                         \
        int k0 = c << 5;                                                           \
        uint32_t sA = sb + st * STAGE;                                             \
        _Pragma("unroll")                                                          \
        for (int i = 0; i < 4; i++) {                                              \
            int ch = tid + i * 256;                                                \
            int row = ch >> 3, seg = ch & 7;                                       \
            cpa16(sA + row * ASTF + seg * 16,                                      \
                  Ag + (size_t)(m0 + row) * (K) + k0 + seg * 4);                   \
            cpa16(sA + B_OFF + row * ASTF + seg * 16,                              \
                  Bt + (size_t)(n0 + row) * (K) + k0 + seg * 4);                   \
        }                                                                          \
    };                                                                             \
    load_stage(0, 0); CP_COMMIT();                                                 \
    for (int c = 0; c < nc; c++) {                                                 \
        if (c + 1 < nc) { load_stage(c + 1, (c + 1) & 1); CP_COMMIT(); CP_WAIT1(); }\
        else { CP_WAIT0(); }                                                       \
        __syncthreads();                                                           \
        uint32_t stOff = (uint32_t)(c & 1) * STAGE;                                \
        _Pragma("unroll")                                                          \
        for (int s = 0; s < 4; s++) {                                              \
            uint32_t ah[2][4], br[4][4];                                           \
            _Pragma("unroll")                                                      \
            for (int mt = 0; mt < 2; mt++)                                         \
                ldsm4(ah[mt], aBase + stOff + mt * 16 * ASTF + s * 32);            \
            _Pragma("unroll")                                                      \
            for (int nt2 = 0; nt2 < 4; nt2++)                                      \
                ldsm4(br[nt2], bBase + stOff + nt2 * 16 * ASTF + s * 32);          \
            _Pragma("unroll")                                                      \
            for (int nt2 = 0; nt2 < 4; nt2++)                                      \
                _Pragma("unroll")                                                  \
                for (int mt = 0; mt < 2; mt++) {                                   \
                    mma_tf32(acc[mt][2 * nt2],     ah[mt], br[nt2][0], br[nt2][2]);\
                    mma_tf32(acc[mt][2 * nt2 + 1], ah[mt], br[nt2][1], br[nt2][3]);\
                }                                                                  \
        }                                                                          \
        __syncthreads();                                                           \
    }

// EPI 1: Ct(tf32 fp32) = gelu(A@B + bias)
// EPI 2: C = resid + mod[b, modOff+n] * (A@B)              (N == 1024)
// EPI 3: C = resid + mod[b, modOff+n] * (A@B + bias)       (N == 1024)
template <int EPI>
__global__ void __launch_bounds__(256, 2)
mma_gemm(const float* __restrict__ Ag, const float* __restrict__ Bt,
         float* __restrict__ C, float* __restrict__ Ct,
         int M, int N, int K,
         const float* __restrict__ bias,
         const float* __restrict__ resid,
         const float* __restrict__ mod, int modOff) {
    extern __shared__ char smem[];
    uint32_t sb = smem_u32(smem);
    int tid = threadIdx.x, lane = tid & 31, wid = tid >> 5;
    int wm = wid >> 1, wn = wid & 1;
    int m0 = blockIdx.y * 128, n0 = blockIdx.x * 128;

    TF32_MAINLOOP(Ag, Bt, K)

    int r0 = lane >> 2, cp2 = (lane & 3) * 2;
    #pragma unroll
    for (int mt = 0; mt < 2; mt++) {
        #pragma unroll
        for (int nt = 0; nt < 8; nt++) {
            int m = m0 + wm * 32 + mt * 16 + r0;
            int n = n0 + wn * 64 + nt * 8 + cp2;
            float* cacc = acc[mt][nt];
            if (EPI == 1) {
                float2 o0, o1;
                o0.x = to_tf32(gelu_tanh(cacc[0] + bias[n]));
                o0.y = to_tf32(gelu_tanh(cacc[1] + bias[n + 1]));
                o1.x = to_tf32(gelu_tanh(cacc[2] + bias[n]));
                o1.y = to_tf32(gelu_tanh(cacc[3] + bias[n + 1]));
                *(float2*)&Ct[(size_t)m * N + n] = o0;
                *(float2*)&Ct[(size_t)(m + 8) * N + n] = o1;
            } else {
                float2 o0, o1;
                o0.x = epi_apply<EPI>(cacc[0], m, n,     N, bias, resid, mod, modOff);
                o0.y = epi_apply<EPI>(cacc[1], m, n + 1, N, bias, resid, mod, modOff);
                o1.x = epi_apply<EPI>(cacc[2], m + 8, n,     N, bias, resid, mod, modOff);
                o1.y = epi_apply<EPI>(cacc[3], m + 8, n + 1, N, bias, resid, mod, modOff);
                *(float2*)&C[(size_t)m * N + n] = o0;
                *(float2*)&C[(size_t)(m + 8) * N + n] = o1;
            }
        }
    }
}

// ---------------- K2: QKV GEMM + fused RMSNorm/RoPE epilogue -----------------
// Each warp's 64 cols = one (t, head). q/k -> tf32 fp32 planes, v -> bf16 split.
__global__ void __launch_bounds__(256, 2)
mma_gemm_qkv(const float* __restrict__ Ag, const float* __restrict__ Bt,
             const float* __restrict__ cosb, const float* __restrict__ sinb,
             const float* __restrict__ qw, const float* __restrict__ kw,
             float* __restrict__ qf, float* __restrict__ kf,
             __nv_bfloat16* __restrict__ vh, __nv_bfloat16* __restrict__ vl) {
    extern __shared__ char smem[];
    uint32_t sb = smem_u32(smem);
    int tid = threadIdx.x, lane = tid & 31, wid = tid >> 5;
    int wm = wid >> 1, wn = wid & 1;
    int m0 = blockIdx.y * 128, n0 = blockIdx.x * 128;
    const int K = DMODEL;

    TF32_MAINLOOP(Ag, Bt, K)

    int r0 = lane >> 2, cp2 = (lane & 3) * 2;
    int nw = n0 + wn * 64;
    int t = nw >> 10;                 // 0=q 1=k 2=v
    int hh = (nw >> 6) & 15;          // head
    #pragma unroll
    for (int mt = 0; mt < 2; mt++) {
        int mA = m0 + wm * 32 + mt * 16 + r0;
        int mB = mA + 8;
        int sA = mA & (SEQ - 1), sB2 = mB & (SEQ - 1);
        size_t baseA = (((size_t)((mA >> 11) * NHEAD + hh)) * SEQ + sA) * HDIM;
        size_t baseB = (((size_t)((mB >> 11) * NHEAD + hh)) * SEQ + sB2) * HDIM;
        if (t == 2) {
            #pragma unroll
            for (int nt = 0; nt < 8; nt++) {
                int d = nt * 8 + cp2;
                split_store2(vh, vl, baseA + d, acc[mt][nt][0], acc[mt][nt][1]);
                split_store2(vh, vl, baseB + d, acc[mt][nt][2], acc[mt][nt][3]);
            }
        } else {
            const float* w = (t == 0) ? qw : kw;
            float ss0 = 0.f, ss1 = 0.f;
            #pragma unroll
            for (int nt = 0; nt < 8; nt++) {
                ss0 += acc[mt][nt][0] * acc[mt][nt][0] + acc[mt][nt][1] * acc[mt][nt][1];
                ss1 += acc[mt][nt][2] * acc[mt][nt][2] + acc[mt][nt][3] * acc[mt][nt][3];
            }
            ss0 += __shfl_xor_sync(0xffffffffu, ss0, 1);
            ss0 += __shfl_xor_sync(0xffffffffu, ss0, 2);
            ss1 += __shfl_xor_sync(0xffffffffu, ss1, 1);
            ss1 += __shfl_xor_sync(0xffffffffu, ss1, 2);
            float ri0 = rsqrtf(ss0 * (1.0f / HDIM) + 1e-6f);
            float ri1 = rsqrtf(ss1 * (1.0f / HDIM) + 1e-6f);
            float xa[16], xb[16];
            #pragma unroll
            for (int nt = 0; nt < 8; nt++) {
                int d = nt * 8 + cp2;
                float w0 = w[d], w1 = w[d + 1];
                xa[2 * nt]     = acc[mt][nt][0] * ri0 * w0;
                xa[2 * nt + 1] = acc[mt][nt][1] * ri0 * w1;
                xb[2 * nt]     = acc[mt][nt][2] * ri1 * w0;
                xb[2 * nt + 1] = acc[mt][nt][3] * ri1 * w1;
            }
            const float SC = (t == 0) ? 0.125f * 1.4426950408889634f : 1.0f;
            float* of = (t == 0) ? qf : kf;
            #pragma unroll
            for (int nt = 0; nt < 8; nt++) {
                int d = nt * 8 + cp2;
                int p = nt ^ 4;
                float sg = (nt < 4) ? -1.f : 1.f;
                float2 cA = *(const float2*)&cosb[sA * HDIM + d];
                float2 sAv = *(const float2*)&sinb[sA * HDIM + d];
                float2 cB = *(const float2*)&cosb[sB2 * HDIM + d];
                float2 sBv = *(const float2*)&sinb[sB2 * HDIM + d];
                float2 oA, oB;
                oA.x = to_tf32((xa[2 * nt] * cA.x + sg * xa[2 * p] * sAv.x) * SC);
                oA.y = to_tf32((xa[2 * nt + 1] * cA.y + sg * xa[2 * p + 1] * sAv.y) * SC);
                oB.x = to_tf32((xb[2 * nt] * cB.x + sg * xb[2 * p] * sBv.x) * SC);
                oB.y = to_tf32((xb[2 * nt + 1] * cB.y + sg * xb[2 * p + 1] * sBv.y) * SC);
                *(float2*)&of[baseA + d] = oA;
                *(float2*)&of[baseB + d] = oB;
            }
        }
    }
}

// ---------------- K4: flash attention: tf32 QK^T + split-bf16 PV -------------
// smem stage: K fp32 [64 keys x 272B] @0 (17408), V_hi [64x144] @17408,
// V_lo @26624. Stage = 35840, double buffered. Q staged once at sb (128x272).
#define KSTF  272
#define VSTF  144
#define V_OFF 17408
#define FSTAGE 35840
#define FLASH_SMEM (2 * FSTAGE)   // 71680

__global__ void __launch_bounds__(256, 2)
flash_mma(const float* __restrict__ qf, const float* __restrict__ kf,
          const __nv_bfloat16* __restrict__ vh, const __nv_bfloat16* __restrict__ vl,
          float* __restrict__ oattn) {
    extern __shared__ char smem[];
    uint32_t sb = smem_u32(smem);
    int tid = threadIdx.x, lane = tid & 31, wid = tid >> 5;
    int bhid = blockIdx.x;               // b*16 + h
    int h = bhid & 15, b = bhid >> 4;
    int q0 = blockIdx.y * 128;
    size_t hoff = (size_t)bhid * SEQ * HDIM;

    // ---- Q -> smem (temp, 128 rows x 272B) -> registers ----
    #pragma unroll
    for (int i = 0; i < 8; i++) {
        int c = tid + i * 256;            // 2048 16B chunks
        int row = c >> 4, seg = c & 15;
        cpa16(sb + row * KSTF + seg * 16, qf + hoff + (size_t)(q0 + row) * HDIM + seg * 4);
    }
    CP_COMMIT(); CP_WAIT0();
    __syncthreads();
    uint32_t qfr[8][4];
    {
        uint32_t aB = sb + (uint32_t)(wid * 16 + (lane & 15)) * KSTF + (uint32_t)(lane >> 4) * 16;
        #pragma unroll
        for (int s = 0; s < 8; s++) ldsm4(qfr[s], aB + s * 32);
    }
    __syncthreads();

    float o[8][4];
    #pragma unroll
    for (int i = 0; i < 8; i++)
        #pragma unroll
        for (int j = 0; j < 4; j++) o[i][j] = 0.f;
    float m0 = -1e30f, m1 = -1e30f, l0 = 0.f, l1 = 0.f;

    uint32_t kBase = (uint32_t)(lane & 15) * KSTF + (uint32_t)(lane >> 4) * 16;
    int bg = lane >> 3;
    uint32_t vB = (uint32_t)((bg & 1) * 8 + (lane & 7)) * VSTF + (uint32_t)((bg >> 1)) * 16;

    auto load_kv = [&](int t, int st) {
        int k0 = t * 64;
        uint32_t sbase = sb + st * FSTAGE;
        #pragma unroll
        for (int i = 0; i < 4; i++) {       // K: 1024 chunks
            int c = tid + i * 256;
            int row = c >> 4, seg = c & 15;
            cpa16(sbase + row * KSTF + seg * 16,
                  kf + hoff + (size_t)(k0 + row) * HDIM + seg * 4);
        }
        #pragma unroll
        for (int i = 0; i < 2; i++) {       // V planes: 512 chunks each
            int c = tid + i * 256;
            int row = c >> 3, seg = c & 7;
            size_t goff = hoff + (size_t)(k0 + row) * HDIM + seg * 8;
            uint32_t d = sbase + V_OFF + row * VSTF + seg * 16;
            cpa16(d, vh + goff);
            cpa16(d + 9216, vl + goff);
        }
    };

    load_kv(0, 0);
    CP_COMMIT();

    const int NT = SEQ / 64;
    for (int t = 0; t < NT; t++) {
        if (t + 1 < NT) {
            load_kv(t + 1, (t + 1) & 1);
            CP_COMMIT();
            CP_WAIT1();
        } else {
            CP_WAIT0();
        }
        __syncthreads();
        uint32_t stB = sb + (uint32_t)(t & 1) * FSTAGE;

        // ---- S = Q K^T (tf32, single pass) ----
        float s[8][4];
        #pragma unroll
        for (int i = 0; i < 8; i++)
            #pragma unroll
            for (int j = 0; j < 4; j++) s[i][j] = 0.f;
        #pragma unroll
        for (int ks = 0; ks < 8; ks++) {
            #pragma unroll
            for (int kg = 0; kg < 4; kg++) {
                uint32_t kr[4];
                ldsm4(kr, stB + kBase + kg * 16 * KSTF + ks * 32);
                mma_tf32(s[kg * 2],     qfr[ks], kr[0], kr[2]);
                mma_tf32(s[kg * 2 + 1], qfr[ks], kr[1], kr[3]);
            }
        }

        // ---- online softmax (base-2; scale folded into Q) ----
        float tm0 = -1e30f, tm1 = -1e30f;
        #pragma unroll
        for (int i = 0; i < 8; i++) {
            tm0 = fmaxf(tm0, fmaxf(s[i][0], s[i][1]));
            tm1 = fmaxf(tm1, fmaxf(s[i][2], s[i][3]));
        }
        tm0 = fmaxf(tm0, __shfl_xor_sync(0xffffffffu, tm0, 1));
        tm0 = fmaxf(tm0, __shfl_xor_sync(0xffffffffu, tm0, 2));
        tm1 = fmaxf(tm1, __shfl_xor_sync(0xffffffffu, tm1, 1));
        tm1 = fmaxf(tm1, __shfl_xor_sync(0xffffffffu, tm1, 2));
        float mn0 = fmaxf(m0, tm0), mn1 = fmaxf(m1, tm1);
        float al0 = exp2f(m0 - mn0), al1 = exp2f(m1 - mn1);
        float ts0 = 0.f, ts1 = 0.f;
        #pragma unroll
        for (int i = 0; i < 8; i++) {
            s[i][0] = exp2f(s[i][0] - mn0);
            s[i][1] = exp2f(s[i][1] - mn0);
            s[i][2] = exp2f(s[i][2] - mn1);
            s[i][3] = exp2f(s[i][3] - mn1);
            ts0 += s[i][0] + s[i][1];
            ts1 += s[i][2] + s[i][3];
        }
        ts0 += __shfl_xor_sync(0xffffffffu, ts0, 1);
        ts0 += __shfl_xor_sync(0xffffffffu, ts0, 2);
        ts1 += __shfl_xor_sync(0xffffffffu, ts1, 1);
        ts1 += __shfl_xor_sync(0xffffffffu, ts1, 2);
        l0 = l0 * al0 + ts0;
        l1 = l1 * al1 + ts1;
        m0 = mn0; m1 = mn1;
        #pragma unroll
        for (int i = 0; i < 8; i++) {
            o[i][0] *= al0; o[i][1] *= al0;
            o[i][2] *= al1; o[i][3] *= al1;
        }

        // ---- O += P V (split P in-register, split V, 3 passes bf16) ----
        #pragma unroll
        for (int kt2 = 0; kt2 < 4; kt2++) {
            uint32_t ph[4], pl[4];
            ph[0] = split_pack(s[kt2 * 2][0],     s[kt2 * 2][1],     pl[0]);
            ph[1] = split_pack(s[kt2 * 2][2],     s[kt2 * 2][3],     pl[1]);
            ph[2] = split_pack(s[kt2 * 2 + 1][0], s[kt2 * 2 + 1][1], pl[2]);
            ph[3] = split_pack(s[kt2 * 2 + 1][2], s[kt2 * 2 + 1][3], pl[3]);
            #pragma unroll
            for (int nq = 0; nq < 4; nq++) {
                uint32_t wh[4], wl[4];
                uint32_t addr = stB + V_OFF + vB + kt2 * 16 * VSTF + nq * 32;
                ldsm4t(wh, addr);
                ldsm4t(wl, addr + 9216);
                mma16816(o[nq * 2],     ph, wh);
                mma16816(o[nq * 2],     pl, wh);
                mma16816(o[nq * 2],     ph, wl);
                mma16816(o[nq * 2 + 1], ph, wh + 2);
                mma16816(o[nq * 2 + 1], pl, wh + 2);
                mma16816(o[nq * 2 + 1], ph, wl + 2);
            }
        }
        __syncthreads();
    }

    // ---- normalize + tf32-rounded store to attn plane [token][D] ----
    float inv0 = 1.f / l0, inv1 = 1.f / l1;
    int r0 = lane >> 2, cp2 = (lane & 3) * 2;
    int row0 = q0 + wid * 16 + r0;
    size_t t0 = (size_t)(b * SEQ + row0) * DMODEL + h * HDIM;
    size_t t1 = t0 + 8 * DMODEL;
    #pragma unroll
    for (int nt = 0; nt < 8; nt++) {
        float2 a, c2;
        a.x = to_tf32(o[nt][0] * inv0);
        a.y = to_tf32(o[nt][1] * inv0);
        c2.x = to_tf32(o[nt][2] * inv1);
        c2.y = to_tf32(o[nt][3] * inv1);
        *(float2*)&oattn[t0 + nt * 8 + cp2] = a;
        *(float2*)&oattn[t1 + nt * 8 + cp2] = c2;
    }
}

// ---------------- launcher ---------------------------------------------------
extern "C" void kernel_launch(void* const* d_in, const int* in_sizes, int n_in,
                              void* d_out, int out_size) {
    const float* x       = (const float*)d_in[0];
    const float* cosb    = (const float*)d_in[1];
    const float* sinb    = (const float*)d_in[2];
    const float* c       = (const float*)d_in[3];
    const float* norm1_w = (const float*)d_in[4];
    const float* Wqkv    = (const float*)d_in[5];
    const float* Wout    = (const float*)d_in[6];
    const float* q_norm_w= (const float*)d_in[7];
    const float* k_norm_w= (const float*)d_in[8];
    const float* norm2_w = (const float*)d_in[9];
    const float* W1      = (const float*)d_in[10];
    const float* b1      = (const float*)d_in[11];
    const float* W2      = (const float*)d_in[12];
    const float* b2      = (const float*)d_in[13];
    const float* ada_W   = (const float*)d_in[14];
    const float* ada_b   = (const float*)d_in[15];
    float* out = (float*)d_out;

    float *mod_p, *xn_p, *attn_p, *h_p;
    float *wqt, *wot, *w1t, *w2t, *q_p, *k_p;
    __nv_bfloat16 *vph, *vpl;
    cudaGetSymbolAddress((void**)&mod_p, g_mod);
    cudaGetSymbolAddress((void**)&xn_p, g_xn);
    cudaGetSymbolAddress((void**)&attn_p, g_attn);
    cudaGetSymbolAddress((void**)&h_p, g_h);
    cudaGetSymbolAddress((void**)&wqt, g_wqkv_t);
    cudaGetSymbolAddress((void**)&wot, g_wout_t);
    cudaGetSymbolAddress((void**)&w1t, g_w1_t);
    cudaGetSymbolAddress((void**)&w2t, g_w2_t);
    cudaGetSymbolAddress((void**)&q_p, g_q);
    cudaGetSymbolAddress((void**)&k_p, g_k);
    cudaGetSymbolAddress((void**)&vph, g_v_hi);
    cudaGetSymbolAddress((void**)&vpl, g_v_lo);

    cudaFuncSetAttribute(mma_gemm<1>, cudaFuncAttributeMaxDynamicSharedMemorySize, GEMM_SMEM);
    cudaFuncSetAttribute(mma_gemm<2>, cudaFuncAttributeMaxDynamicSharedMemorySize, GEMM_SMEM);
    cudaFuncSetAttribute(mma_gemm<3>, cudaFuncAttributeMaxDynamicSharedMemorySize, GEMM_SMEM);
    cudaFuncSetAttribute(mma_gemm_qkv, cudaFuncAttributeMaxDynamicSharedMemorySize, GEMM_SMEM);
    cudaFuncSetAttribute(flash_mma, cudaFuncAttributeMaxDynamicSharedMemorySize, FLASH_SMEM);

    // weight transpose + tf32 round: Wt[n][k]
    transp_w<<<dim3(3 * DMODEL / 32, DMODEL / 32), 256>>>(Wqkv, wqt, DMODEL, 3 * DMODEL);
    transp_w<<<dim3(DMODEL / 32, DMODEL / 32), 256>>>(Wout, wot, DMODEL, DMODEL);
    transp_w<<<dim3(DFF / 32, DMODEL / 32), 256>>>(W1, w1t, DMODEL, DFF);
    transp_w<<<dim3(DMODEL / 32, DFF / 32), 256>>>(W2, w2t, DFF, DMODEL);

    // K0: modulation
    ada_kernel<<<MODW / 256, 256>>>(c, ada_W, ada_b, mod_p);

    // K1: LN1 + modulate -> xn tf32 plane
    ln_mod_kernel<<<TOKENS, 256>>>(x, norm1_w, mod_p, 0, 1024, xn_p);

    // K2: QKV GEMM + fused RMSNorm/RoPE -> q/k tf32 planes, v bf16 split
    mma_gemm_qkv<<<dim3(3 * DMODEL / 128, TOKENS / 128), 256, GEMM_SMEM>>>(
        xn_p, wqt, cosb, sinb, q_norm_w, k_norm_w, q_p, k_p, vph, vpl);

    // K4: flash attention -> attn tf32 plane
    flash_mma<<<dim3(BATCH * NHEAD, SEQ / 128), 256, FLASH_SMEM>>>(
        q_p, k_p, vph, vpl, attn_p);

    // K5: Wout GEMM + gated residual (g_msa @2048) -> out fp32
    mma_gemm<2><<<dim3(DMODEL / 128, TOKENS / 128), 256, GEMM_SMEM>>>(
        attn_p, wot, out, nullptr, TOKENS, DMODEL, DMODEL, nullptr, x, mod_p, 2048);

    // K6: LN2 + modulate -> xn tf32 plane
    ln_mod_kernel<<<TOKENS, 256>>>(out, norm2_w, mod_p, 3072, 4096, xn_p);

    // K7: MLP up GEMM + bias + gelu -> h tf32 plane
    mma_gemm<1><<<dim3(DFF / 128, TOKENS / 128), 256, GEMM_SMEM>>>(
        xn_p, w1t, nullptr, h_p, TOKENS, DFF, DMODEL, b1, nullptr, nullptr, 0);

    // K8: MLP down GEMM + bias + gated residual (g_mlp @5120), in-place on out
    mma_gemm<3><<<dim3(DMODEL / 128, TOKENS / 128), 256, GEMM_SMEM>>>(
        h_p, w2t, out, nullptr, TOKENS, DMODEL, DFF, b2, out, mod_p, 5120);
}